// round 5
// baseline (speedup 1.0000x reference)
#include <cuda_runtime.h>
#include <cstdint>
#include <math.h>

// Problem constants
constexpr int Bb  = 2;
constexpr int Ss  = 2048;
constexpr int Ee  = 2048;
constexpr int Hh  = 32;
constexpr int HKVv= 8;
constexpr int Dd  = 64;
constexpr int MS  = Bb * Ss;      // 4096 rows

// ---------------------------------------------------------------------------
// Scratch (no cudaMalloc allowed). All "split" arrays are bf16 pairs packed
// in uint32 (low half = even element).
// ---------------------------------------------------------------------------
__device__ uint32_t s_xh[MS * Ee / 2],  s_xl[MS * Ee / 2];
__device__ uint32_t s_wqh[Ee * Ee / 2], s_wql[Ee * Ee / 2];
__device__ uint32_t s_wkh[512 * Ee / 2], s_wkl[512 * Ee / 2];
__device__ uint32_t s_wvh[512 * Ee / 2], s_wvl[512 * Ee / 2];
__device__ uint32_t s_woh[Ee * Ee / 2], s_wol[Ee * Ee / 2];
__device__ float    g_q[MS * 2048];
__device__ float    g_k[MS * 512];
__device__ float    g_v[MS * 512];
__device__ uint32_t s_qh[MS * 1024], s_ql[MS * 1024];
__device__ uint32_t s_kh[MS * 256],  s_kl[MS * 256];
__device__ uint32_t s_vh[MS * 256],  s_vl[MS * 256];
__device__ uint32_t s_ah[MS * 1024], s_al[MS * 1024];

// ---------------------------------------------------------------------------
// Helpers
// ---------------------------------------------------------------------------
__device__ __forceinline__ uint32_t smem_u32(const void* p) {
    uint32_t a;
    asm("{ .reg .u64 t; cvta.to.shared.u64 t, %1; cvt.u32.u64 %0, t; }" : "=r"(a) : "l"(p));
    return a;
}

#define LDX4(r0, r1, r2, r3, addr) \
    asm volatile("ldmatrix.sync.aligned.m8n8.x4.shared.b16 {%0,%1,%2,%3}, [%4];" \
        : "=r"(r0), "=r"(r1), "=r"(r2), "=r"(r3) : "r"(addr))

#define LDX4T(r0, r1, r2, r3, addr) \
    asm volatile("ldmatrix.sync.aligned.m8n8.x4.trans.shared.b16 {%0,%1,%2,%3}, [%4];" \
        : "=r"(r0), "=r"(r1), "=r"(r2), "=r"(r3) : "r"(addr))

#define CP_ASYNC16(dst, src) \
    asm volatile("cp.async.cg.shared.global [%0], [%1], 16;" :: "r"(dst), "l"(src))
#define CP_COMMIT() asm volatile("cp.async.commit_group;")
#define CP_WAIT(n)  asm volatile("cp.async.wait_group %0;" :: "n"(n))

__device__ __forceinline__ void mma_bf16(float c[4], const uint32_t a[4], const uint32_t b[2]) {
    asm volatile("mma.sync.aligned.m16n8k16.row.col.f32.bf16.bf16.f32 "
                 "{%0,%1,%2,%3}, {%4,%5,%6,%7}, {%8,%9}, {%0,%1,%2,%3};"
                 : "+f"(c[0]), "+f"(c[1]), "+f"(c[2]), "+f"(c[3])
                 : "r"(a[0]), "r"(a[1]), "r"(a[2]), "r"(a[3]), "r"(b[0]), "r"(b[1]));
}

// rne pack: {bf16(x1) : bf16(x0)}
__device__ __forceinline__ uint32_t packf(float x0, float x1) {
    uint32_t r;
    asm("cvt.rn.bf16x2.f32 %0, %1, %2;" : "=r"(r) : "f"(x1), "f"(x0));
    return r;
}
// residual pack given rne-pack ph of (x0,x1)
__device__ __forceinline__ uint32_t packlo(uint32_t ph, float x0, float x1) {
    float r0 = x0 - __uint_as_float(ph << 16);
    float r1 = x1 - __uint_as_float(ph & 0xFFFF0000u);
    return packf(r0, r1);
}

// ---------------------------------------------------------------------------
// split kernel: fp32 -> (hi bf16x2, lo bf16x2), 4 floats per thread
// ---------------------------------------------------------------------------
__global__ void split_kernel(const float4* __restrict__ src,
                             uint2* __restrict__ hi, uint2* __restrict__ lo, int n4)
{
    int i = blockIdx.x * blockDim.x + threadIdx.x;
    if (i >= n4) return;
    float4 f = src[i];
    uint32_t h0 = packf(f.x, f.y), h1 = packf(f.z, f.w);
    hi[i] = make_uint2(h0, h1);
    lo[i] = make_uint2(packlo(h0, f.x, f.y), packlo(h1, f.z, f.w));
}

// ---------------------------------------------------------------------------
// Pure-bf16 split GEMM: C[M,N] = A[M,K] * W[N,K]^T, K=2048 fixed.
// A/B pre-split hi/lo bf16. 128x128 tile, BK=32, 3-stage cp.async.
// smem rows: 32 bf16 = 64B + 16B pad = 80B.
// ---------------------------------------------------------------------------
constexpr int GB_ROW   = 80;
constexpr int GB_TILE  = 128 * GB_ROW;     // 10240
constexpr int GB_STAGE = 4 * GB_TILE;      // 40960 (Ahi,Alo,Bhi,Blo)
constexpr int GB_SMEM  = 3 * GB_STAGE;     // 122880

__device__ __forceinline__ void gemm_core(
    const char* Ah, const char* Al, const char* Bh, const char* Bl,
    float* C, int ldc, char* smem)
{
    const uint32_t sbase = smem_u32(smem);
    const int tid  = threadIdx.x;
    const int wid  = tid >> 5;
    const int lane = tid & 31;
    const int m0 = blockIdx.y * 128;
    const int n0 = blockIdx.x * 128;
    const int wm = wid & 1;
    const int wn = wid >> 1;
    const int lmrow = lane & 15;
    const int lmk   = (lane >> 4) * 16;

    float acc[4][4][4];
#pragma unroll
    for (int i = 0; i < 4; ++i)
#pragma unroll
        for (int j = 0; j < 4; ++j)
#pragma unroll
            for (int r = 0; r < 4; ++r) acc[i][j][r] = 0.f;

    // stage issue: 2048 x 16B chunks, 8 per thread
    auto issue = [&](int kt, int s) {
#pragma unroll
        for (int c = 0; c < 8; ++c) {
            int ch  = c * 256 + tid;
            int arr = ch >> 9;          // 0=Ah 1=Al 2=Bh 3=Bl
            int r   = (ch >> 2) & 127;
            int c16 = ch & 3;
            const char* g;
            if      (arr == 0) g = Ah + (size_t)(m0 + r) * 4096 + kt * 64 + c16 * 16;
            else if (arr == 1) g = Al + (size_t)(m0 + r) * 4096 + kt * 64 + c16 * 16;
            else if (arr == 2) g = Bh + (size_t)(n0 + r) * 4096 + kt * 64 + c16 * 16;
            else               g = Bl + (size_t)(n0 + r) * 4096 + kt * 64 + c16 * 16;
            uint32_t dst = sbase + s * GB_STAGE + arr * GB_TILE + r * GB_ROW + c16 * 16;
            CP_ASYNC16(dst, g);
        }
        CP_COMMIT();
    };

    issue(0, 0);
    issue(1, 1);

    constexpr int NT = 64;   // 2048 / 32
    for (int kt = 0; kt < NT; ++kt) {
        const int s = kt % 3;
        if (kt + 2 < NT) { issue(kt + 2, (kt + 2) % 3); CP_WAIT(2); }
        else if (kt + 1 < NT) { CP_WAIT(1); }
        else { CP_WAIT(0); }
        __syncthreads();

        const uint32_t tb = sbase + s * GB_STAGE;
#pragma unroll
        for (int ks = 0; ks < 2; ++ks) {
            const int kb = ks * 32 + lmk;
            uint32_t bh[4][2], bl[4][2];
#pragma unroll
            for (int g16 = 0; g16 < 2; ++g16) {
                uint32_t r0, r1, r2, r3;
                LDX4(r0, r1, r2, r3,
                     tb + 2 * GB_TILE + (uint32_t)(wn * 32 + g16 * 16 + lmrow) * GB_ROW + kb);
                bh[g16 * 2][0] = r0; bh[g16 * 2][1] = r2;
                bh[g16 * 2 + 1][0] = r1; bh[g16 * 2 + 1][1] = r3;
                LDX4(r0, r1, r2, r3,
                     tb + 3 * GB_TILE + (uint32_t)(wn * 32 + g16 * 16 + lmrow) * GB_ROW + kb);
                bl[g16 * 2][0] = r0; bl[g16 * 2][1] = r2;
                bl[g16 * 2 + 1][0] = r1; bl[g16 * 2 + 1][1] = r3;
            }
            uint32_t af[4][4];
#pragma unroll
            for (int mt = 0; mt < 4; ++mt)
                LDX4(af[mt][0], af[mt][1], af[mt][2], af[mt][3],
                     tb + (uint32_t)(wm * 64 + mt * 16 + lmrow) * GB_ROW + kb);
#pragma unroll
            for (int mt = 0; mt < 4; ++mt)
#pragma unroll
                for (int nt = 0; nt < 4; ++nt) {
                    mma_bf16(acc[mt][nt], af[mt], bh[nt]);
                    mma_bf16(acc[mt][nt], af[mt], bl[nt]);
                }
#pragma unroll
            for (int mt = 0; mt < 4; ++mt)
                LDX4(af[mt][0], af[mt][1], af[mt][2], af[mt][3],
                     tb + GB_TILE + (uint32_t)(wm * 64 + mt * 16 + lmrow) * GB_ROW + kb);
#pragma unroll
            for (int mt = 0; mt < 4; ++mt)
#pragma unroll
                for (int nt = 0; nt < 4; ++nt)
                    mma_bf16(acc[mt][nt], af[mt], bh[nt]);
        }
        __syncthreads();
    }

    // epilogue
    const int g = lane >> 2;
    const int t = lane & 3;
#pragma unroll
    for (int mt = 0; mt < 4; ++mt) {
#pragma unroll
        for (int nt = 0; nt < 4; ++nt) {
            int r = m0 + wm * 64 + mt * 16 + g;
            int c = n0 + wn * 32 + nt * 8 + t * 2;
            *(float2*)(C + (size_t)r * ldc + c)       = make_float2(acc[mt][nt][0], acc[mt][nt][1]);
            *(float2*)(C + (size_t)(r + 8) * ldc + c) = make_float2(acc[mt][nt][2], acc[mt][nt][3]);
        }
    }
}

__global__ void __launch_bounds__(256, 1) gemm_bf16_kernel(
    const void* Ah, const void* Al, const void* Bh, const void* Bl,
    float* C, int ldc)
{
    extern __shared__ char smem[];
    gemm_core((const char*)Ah, (const char*)Al, (const char*)Bh, (const char*)Bl,
              C, ldc, smem);
}

// merged K/V projection (blockIdx.z selects weight/output)
__global__ void __launch_bounds__(256, 1) gemm_bf16_kv_kernel(
    const void* Ah, const void* Al,
    const void* Bh0, const void* Bl0, float* C0,
    const void* Bh1, const void* Bl1, float* C1)
{
    extern __shared__ char smem[];
    const void* Bh = blockIdx.z ? Bh1 : Bh0;
    const void* Bl = blockIdx.z ? Bl1 : Bl0;
    float* C = blockIdx.z ? C1 : C0;
    gemm_core((const char*)Ah, (const char*)Al, (const char*)Bh, (const char*)Bl,
              C, 512, smem);
}

// ---------------------------------------------------------------------------
// Fused rope + hi/lo split for q,k; plain split for v.
// ---------------------------------------------------------------------------
__global__ void rope_conv_kernel(
    const float* __restrict__ q, const float* __restrict__ k, const float* __restrict__ v,
    const float* __restrict__ cosb, const float* __restrict__ sinb,
    uint32_t* __restrict__ qh, uint32_t* __restrict__ ql,
    uint32_t* __restrict__ kh, uint32_t* __restrict__ kl,
    uint32_t* __restrict__ vh, uint32_t* __restrict__ vl)
{
    const int NQr = MS * Hh * 16;     // 2097152
    const int NKr = MS * HKVv * 16;   // 524288
    const int NV  = MS * 256;         // 1048576 (pairs)
    int idx = blockIdx.x * blockDim.x + threadIdx.x;
    if (idx < NQr) {
        int j = idx & 15;
        int t = idx >> 4;             // row*32 + h
        int s = (t >> 5) & (Ss - 1);
        int d0 = 2 * j;
        const float* p = q + (size_t)t * 64;
        float x0 = p[d0], x1 = p[d0 + 1], x2 = p[d0 + 32], x3 = p[d0 + 33];
        const float* cb = cosb + s * 64;
        const float* sbn = sinb + s * 64;
        float y0 = x0 * cb[d0]      - x2 * sbn[d0];
        float y1 = x1 * cb[d0 + 1]  - x3 * sbn[d0 + 1];
        float y2 = x2 * cb[d0 + 32] + x0 * sbn[d0 + 32];
        float y3 = x3 * cb[d0 + 33] + x1 * sbn[d0 + 33];
        uint32_t h0 = packf(y0, y1);
        uint32_t h1 = packf(y2, y3);
        qh[(size_t)t * 32 + j]      = h0;
        ql[(size_t)t * 32 + j]      = packlo(h0, y0, y1);
        qh[(size_t)t * 32 + 16 + j] = h1;
        ql[(size_t)t * 32 + 16 + j] = packlo(h1, y2, y3);
    } else if (idx < NQr + NKr) {
        int i2 = idx - NQr;
        int j = i2 & 15;
        int t = i2 >> 4;              // row*8 + hkv
        int s = (t >> 3) & (Ss - 1);
        int d0 = 2 * j;
        const float* p = k + (size_t)t * 64;
        float x0 = p[d0], x1 = p[d0 + 1], x2 = p[d0 + 32], x3 = p[d0 + 33];
        const float* cb = cosb + s * 64;
        const float* sbn = sinb + s * 64;
        float y0 = x0 * cb[d0]      - x2 * sbn[d0];
        float y1 = x1 * cb[d0 + 1]  - x3 * sbn[d0 + 1];
        float y2 = x2 * cb[d0 + 32] + x0 * sbn[d0 + 32];
        float y3 = x3 * cb[d0 + 33] + x1 * sbn[d0 + 33];
        uint32_t h0 = packf(y0, y1);
        uint32_t h1 = packf(y2, y3);
        kh[(size_t)t * 32 + j]      = h0;
        kl[(size_t)t * 32 + j]      = packlo(h0, y0, y1);
        kh[(size_t)t * 32 + 16 + j] = h1;
        kl[(size_t)t * 32 + 16 + j] = packlo(h1, y2, y3);
    } else if (idx < NQr + NKr + NV) {
        int i = idx - NQr - NKr;
        float x0 = v[2 * i], x1 = v[2 * i + 1];
        uint32_t h = packf(x0, x1);
        vh[i] = h;
        vl[i] = packlo(h, x0, x1);
    }
}

// ---------------------------------------------------------------------------
// Flash attention, bf16-split mma.sync, pre-split inputs, cp.async KV pipeline.
// Block 256 thr (8 warps), Q tile 128 (16 rows/warp), KV tile 64.
// smem rows 144B (9 x 16B, conflict-free).
// ---------------------------------------------------------------------------
constexpr int AROW   = 144;
constexpr int A_QH   = 0;
constexpr int A_QL   = A_QH + 128 * AROW;      // 18432
constexpr int A_KV0  = A_QL + 128 * AROW;      // 36864
constexpr int KV_ARR = 64 * AROW;              // 9216 (KH,KL,VH,VL)
constexpr int KVSTAGE = 4 * KV_ARR;            // 36864
constexpr int A_SMEM  = A_KV0 + 2 * KVSTAGE;   // 110592

__global__ void __launch_bounds__(256, 1) attn_mma_kernel(
    const uint32_t* __restrict__ qh_g, const uint32_t* __restrict__ ql_g,
    const uint32_t* __restrict__ kh_g, const uint32_t* __restrict__ kl_g,
    const uint32_t* __restrict__ vh_g, const uint32_t* __restrict__ vl_g,
    uint32_t* __restrict__ ah_g, uint32_t* __restrict__ al_g)
{
    extern __shared__ char sm[];
    const uint32_t sb = smem_u32(sm);
    const int tid  = threadIdx.x;
    const int wid  = tid >> 5;
    const int lane = tid & 31;
    const int q0 = blockIdx.x * 128;
    const int h  = blockIdx.y;
    const int b  = blockIdx.z;
    const int hkv = h >> 2;

    const int lmrow  = lane & 15;
    const int lmk    = (lane >> 4) * 16;

    // KV stage issue: 2048 chunks of 16B, 8 per thread
    auto issue_kv = [&](int t, int s) {
#pragma unroll
        for (int c = 0; c < 8; ++c) {
            int ch  = c * 256 + tid;
            int arr = ch >> 9;          // 0=KH 1=KL 2=VH 3=VL
            int r   = (ch >> 3) & 63;
            int c16 = ch & 7;
            const uint32_t* gsrc;
            if      (arr == 0) gsrc = kh_g;
            else if (arr == 1) gsrc = kl_g;
            else if (arr == 2) gsrc = vh_g;
            else               gsrc = vl_g;
            const char* g = (const char*)gsrc
                + ((size_t)(b * Ss + t * 64 + r) * 256 + hkv * 32) * 4 + c16 * 16;
            uint32_t dst = sb + A_KV0 + s * KVSTAGE + arr * KV_ARR + r * AROW + c16 * 16;
            CP_ASYNC16(dst, g);
        }
        CP_COMMIT();
    };

    issue_kv(0, 0);

    // ---- stage Q (plain loads, once) ----
#pragma unroll
    for (int c = 0; c < 8; ++c) {
        int ch  = c * 256 + tid;
        int arr = ch >> 10;             // 0=QH 1=QL
        int r   = (ch >> 3) & 127;
        int c16 = ch & 7;
        const char* src = (const char*)(arr ? ql_g : qh_g)
            + ((size_t)(b * Ss + q0 + r) * 1024 + h * 32) * 4 + c16 * 16;
        *(uint4*)(sm + (arr ? A_QL : A_QH) + r * AROW + c16 * 16) = *(const uint4*)src;
    }
    __syncthreads();

    // ---- hoist Q fragments into registers ----
    uint32_t qfh[4][4], qfl[4][4];
#pragma unroll
    for (int kd = 0; kd < 4; ++kd) {
        LDX4(qfh[kd][0], qfh[kd][1], qfh[kd][2], qfh[kd][3],
             sb + A_QH + (uint32_t)(wid * 16 + lmrow) * AROW + kd * 32 + lmk);
        LDX4(qfl[kd][0], qfl[kd][1], qfl[kd][2], qfl[kd][3],
             sb + A_QL + (uint32_t)(wid * 16 + lmrow) * AROW + kd * 32 + lmk);
    }

    float o[8][4];
#pragma unroll
    for (int j = 0; j < 8; ++j)
#pragma unroll
        for (int r = 0; r < 4; ++r) o[j][r] = 0.f;
    float mstat[2] = {-1e30f, -1e30f};
    float lstat[2] = {0.f, 0.f};

    for (int t = 0; t < Ss / 64; ++t) {
        const int s = t & 1;
        if (t + 1 < Ss / 64) { issue_kv(t + 1, s ^ 1); CP_WAIT(1); }
        else { CP_WAIT(0); }
        __syncthreads();

        const uint32_t kvb = sb + A_KV0 + s * KVSTAGE;

        // ---- S = Q K^T (3-term split) ----
        float sreg[8][4];
#pragma unroll
        for (int j = 0; j < 8; ++j)
#pragma unroll
            for (int r = 0; r < 4; ++r) sreg[j][r] = 0.f;

#pragma unroll
        for (int kd = 0; kd < 4; ++kd) {
#pragma unroll
            for (int j16 = 0; j16 < 4; ++j16) {
                uint32_t h0, h1, h2, h3, l0, l1, l2, l3;
                LDX4(h0, h1, h2, h3,
                     kvb + 0 * KV_ARR + (uint32_t)(j16 * 16 + lmrow) * AROW + kd * 32 + lmk);
                LDX4(l0, l1, l2, l3,
                     kvb + 1 * KV_ARR + (uint32_t)(j16 * 16 + lmrow) * AROW + kd * 32 + lmk);
                uint32_t bh0[2] = {h0, h2}, bh1[2] = {h1, h3};
                uint32_t bl0[2] = {l0, l2}, bl1[2] = {l1, l3};
                mma_bf16(sreg[2 * j16],     qfh[kd], bh0);
                mma_bf16(sreg[2 * j16],     qfh[kd], bl0);
                mma_bf16(sreg[2 * j16],     qfl[kd], bh0);
                mma_bf16(sreg[2 * j16 + 1], qfh[kd], bh1);
                mma_bf16(sreg[2 * j16 + 1], qfh[kd], bl1);
                mma_bf16(sreg[2 * j16 + 1], qfl[kd], bh1);
            }
        }

        // ---- online softmax ----
#pragma unroll
        for (int hf = 0; hf < 2; ++hf) {
            float mx = -1e30f;
#pragma unroll
            for (int j = 0; j < 8; ++j) {
                sreg[j][hf * 2]     *= 0.125f;
                sreg[j][hf * 2 + 1] *= 0.125f;
                mx = fmaxf(mx, fmaxf(sreg[j][hf * 2], sreg[j][hf * 2 + 1]));
            }
            mx = fmaxf(mx, __shfl_xor_sync(0xffffffffu, mx, 1));
            mx = fmaxf(mx, __shfl_xor_sync(0xffffffffu, mx, 2));
            float mnew = fmaxf(mstat[hf], mx);
            float corr = __expf(mstat[hf] - mnew);
            float sum = 0.f;
#pragma unroll
            for (int j = 0; j < 8; ++j) {
                sreg[j][hf * 2]     = __expf(sreg[j][hf * 2] - mnew);
                sreg[j][hf * 2 + 1] = __expf(sreg[j][hf * 2 + 1] - mnew);
                sum += sreg[j][hf * 2] + sreg[j][hf * 2 + 1];
            }
            sum += __shfl_xor_sync(0xffffffffu, sum, 1);
            sum += __shfl_xor_sync(0xffffffffu, sum, 2);
            lstat[hf] = lstat[hf] * corr + sum;
            mstat[hf] = mnew;
#pragma unroll
            for (int j = 0; j < 8; ++j) {
                o[j][hf * 2]     *= corr;
                o[j][hf * 2 + 1] *= corr;
            }
        }

        // ---- O += P V (3-term split) ----
#pragma unroll
        for (int kk = 0; kk < 4; ++kk) {
            uint32_t ah[4], al[4];
            ah[0] = packf(sreg[2 * kk][0],     sreg[2 * kk][1]);
            ah[1] = packf(sreg[2 * kk][2],     sreg[2 * kk][3]);
            ah[2] = packf(sreg[2 * kk + 1][0], sreg[2 * kk + 1][1]);
            ah[3] = packf(sreg[2 * kk + 1][2], sreg[2 * kk + 1][3]);
            al[0] = packlo(ah[0], sreg[2 * kk][0],     sreg[2 * kk][1]);
            al[1] = packlo(ah[1], sreg[2 * kk][2],     sreg[2 * kk][3]);
            al[2] = packlo(ah[2], sreg[2 * kk + 1][0], sreg[2 * kk + 1][1]);
            al[3] = packlo(ah[3], sreg[2 * kk + 1][2], sreg[2 * kk + 1][3]);
#pragma unroll
            for (int j = 0; j < 4; ++j) {
                uint32_t vh0, vh1, vh2, vh3, vl0, vl1, vl2, vl3;
                LDX4T(vh0, vh1, vh2, vh3,
                      kvb + 2 * KV_ARR + (uint32_t)(kk * 16 + lmrow) * AROW + j * 32 + lmk);
                LDX4T(vl0, vl1, vl2, vl3,
                      kvb + 3 * KV_ARR + (uint32_t)(kk * 16 + lmrow) * AROW + j * 32 + lmk);
                uint32_t bh0[2] = {vh0, vh1}, bh1[2] = {vh2, vh3};
                uint32_t bl0[2] = {vl0, vl1}, bl1[2] = {vl2, vl3};
                mma_bf16(o[2 * j],     ah, bh0);
                mma_bf16(o[2 * j],     al, bh0);
                mma_bf16(o[2 * j],     ah, bl0);
                mma_bf16(o[2 * j + 1], ah, bh1);
                mma_bf16(o[2 * j + 1], al, bh1);
                mma_bf16(o[2 * j + 1], ah, bl1);
            }
        }
        __syncthreads();
    }

    // ---- epilogue: write hi/lo bf16 attn output (input to O projection) ----
    const int g  = lane >> 2;
    const int tt = lane & 3;
    const float inv0 = 1.f / lstat[0];
    const float inv1 = 1.f / lstat[1];
    const int mrow = q0 + wid * 16 + g;
    uint32_t* ah0 = ah_g + (size_t)(b * Ss + mrow) * 1024 + h * 32;
    uint32_t* al0 = al_g + (size_t)(b * Ss + mrow) * 1024 + h * 32;
    uint32_t* ah1 = ah0 + (size_t)8 * 1024;
    uint32_t* al1 = al0 + (size_t)8 * 1024;
#pragma unroll
    for (int j = 0; j < 8; ++j) {
        float y0 = o[j][0] * inv0, y1 = o[j][1] * inv0;
        uint32_t ph = packf(y0, y1);
        ah0[j * 4 + tt] = ph;
        al0[j * 4 + tt] = packlo(ph, y0, y1);
        float y2 = o[j][2] * inv1, y3 = o[j][3] * inv1;
        uint32_t ph2 = packf(y2, y3);
        ah1[j * 4 + tt] = ph2;
        al1[j * 4 + tt] = packlo(ph2, y2, y3);
    }
}

// ---------------------------------------------------------------------------
extern "C" void kernel_launch(void* const* d_in, const int* in_sizes, int n_in,
                              void* d_out, int out_size)
{
    (void)in_sizes; (void)n_in; (void)out_size;
    const float* x    = (const float*)d_in[0];
    const float* cosb = (const float*)d_in[1];
    const float* sinb = (const float*)d_in[2];
    const float* Wq   = (const float*)d_in[3];
    const float* Wk   = (const float*)d_in[4];
    const float* Wv   = (const float*)d_in[5];
    const float* Wo   = (const float*)d_in[6];
    float* out = (float*)d_out;

    void *xh, *xl, *wqh, *wql, *wkh, *wkl, *wvh, *wvl, *woh, *wol;
    void *qb, *kb, *vb, *qhp, *qlp, *khp, *klp, *vhp, *vlp, *ahp, *alp;
    cudaGetSymbolAddress(&xh, s_xh);   cudaGetSymbolAddress(&xl, s_xl);
    cudaGetSymbolAddress(&wqh, s_wqh); cudaGetSymbolAddress(&wql, s_wql);
    cudaGetSymbolAddress(&wkh, s_wkh); cudaGetSymbolAddress(&wkl, s_wkl);
    cudaGetSymbolAddress(&wvh, s_wvh); cudaGetSymbolAddress(&wvl, s_wvl);
    cudaGetSymbolAddress(&woh, s_woh); cudaGetSymbolAddress(&wol, s_wol);
    cudaGetSymbolAddress(&qb, g_q);    cudaGetSymbolAddress(&kb, g_k);
    cudaGetSymbolAddress(&vb, g_v);
    cudaGetSymbolAddress(&qhp, s_qh);  cudaGetSymbolAddress(&qlp, s_ql);
    cudaGetSymbolAddress(&khp, s_kh);  cudaGetSymbolAddress(&klp, s_kl);
    cudaGetSymbolAddress(&vhp, s_vh);  cudaGetSymbolAddress(&vlp, s_vl);
    cudaGetSymbolAddress(&ahp, s_ah);  cudaGetSymbolAddress(&alp, s_al);

    cudaFuncSetAttribute(gemm_bf16_kernel, cudaFuncAttributeMaxDynamicSharedMemorySize, GB_SMEM);
    cudaFuncSetAttribute(gemm_bf16_kv_kernel, cudaFuncAttributeMaxDynamicSharedMemorySize, GB_SMEM);
    cudaFuncSetAttribute(attn_mma_kernel, cudaFuncAttributeMaxDynamicSharedMemorySize, A_SMEM);

    // 1) pre-split x and weights
    {
        int n4;
        n4 = MS * Ee / 4;
        split_kernel<<<(n4 + 255) / 256, 256>>>((const float4*)x, (uint2*)xh, (uint2*)xl, n4);
        n4 = Ee * Ee / 4;
        split_kernel<<<(n4 + 255) / 256, 256>>>((const float4*)Wq, (uint2*)wqh, (uint2*)wql, n4);
        n4 = 512 * Ee / 4;
        split_kernel<<<(n4 + 255) / 256, 256>>>((const float4*)Wk, (uint2*)wkh, (uint2*)wkl, n4);
        split_kernel<<<(n4 + 255) / 256, 256>>>((const float4*)Wv, (uint2*)wvh, (uint2*)wvl, n4);
        n4 = Ee * Ee / 4;
        split_kernel<<<(n4 + 255) / 256, 256>>>((const float4*)Wo, (uint2*)woh, (uint2*)wol, n4);
    }

    // 2) projections
    gemm_bf16_kernel<<<dim3(16, 32), 256, GB_SMEM>>>(xh, xl, wqh, wql, (float*)qb, 2048);
    gemm_bf16_kv_kernel<<<dim3(4, 32, 2), 256, GB_SMEM>>>(
        xh, xl, wkh, wkl, (float*)kb, wvh, wvl, (float*)vb);

    // 3) rope + split q,k; split v
    {
        int total = MS * Hh * 16 + MS * HKVv * 16 + MS * 256;
        rope_conv_kernel<<<(total + 255) / 256, 256>>>(
            (const float*)qb, (const float*)kb, (const float*)vb, cosb, sinb,
            (uint32_t*)qhp, (uint32_t*)qlp, (uint32_t*)khp, (uint32_t*)klp,
            (uint32_t*)vhp, (uint32_t*)vlp);
    }

    // 4) attention
    attn_mma_kernel<<<dim3(16, 32, 2), 256, A_SMEM>>>(
        (const uint32_t*)qhp, (const uint32_t*)qlp,
        (const uint32_t*)khp, (const uint32_t*)klp,
        (const uint32_t*)vhp, (const uint32_t*)vlp,
        (uint32_t*)ahp, (uint32_t*)alp);

    // 5) output projection
    gemm_bf16_kernel<<<dim3(16, 32), 256, GB_SMEM>>>(ahp, alp, woh, wol, out, 2048);
}

// round 6
// speedup vs baseline: 1.1060x; 1.1060x over previous
#include <cuda_runtime.h>
#include <cstdint>
#include <math.h>

// Problem constants
constexpr int Bb  = 2;
constexpr int Ss  = 2048;
constexpr int Ee  = 2048;
constexpr int Hh  = 32;
constexpr int HKVv= 8;
constexpr int Dd  = 64;
constexpr int MS  = Bb * Ss;      // 4096 rows

// ---------------------------------------------------------------------------
// Scratch (no cudaMalloc allowed). All "split" arrays are bf16 pairs packed
// in uint32 (low half = even element).
// ---------------------------------------------------------------------------
__device__ uint32_t s_xh[MS * Ee / 2],  s_xl[MS * Ee / 2];
__device__ uint32_t s_wqh[Ee * Ee / 2], s_wql[Ee * Ee / 2];
__device__ uint32_t s_wkh[512 * Ee / 2], s_wkl[512 * Ee / 2];
__device__ uint32_t s_wvh[512 * Ee / 2], s_wvl[512 * Ee / 2];
__device__ uint32_t s_woh[Ee * Ee / 2], s_wol[Ee * Ee / 2];
__device__ float    g_q[MS * 2048];
__device__ float    g_k[MS * 512];
__device__ float    g_v[MS * 512];
__device__ uint32_t s_qh[MS * 1024], s_ql[MS * 1024];
__device__ uint32_t s_kh[MS * 256],  s_kl[MS * 256];
__device__ uint32_t s_vh[MS * 256],  s_vl[MS * 256];
__device__ uint32_t s_ah[MS * 1024], s_al[MS * 1024];

// ---------------------------------------------------------------------------
// Helpers
// ---------------------------------------------------------------------------
__device__ __forceinline__ uint32_t smem_u32(const void* p) {
    uint32_t a;
    asm("{ .reg .u64 t; cvta.to.shared.u64 t, %1; cvt.u32.u64 %0, t; }" : "=r"(a) : "l"(p));
    return a;
}

#define LDX4(r0, r1, r2, r3, addr) \
    asm volatile("ldmatrix.sync.aligned.m8n8.x4.shared.b16 {%0,%1,%2,%3}, [%4];" \
        : "=r"(r0), "=r"(r1), "=r"(r2), "=r"(r3) : "r"(addr))

#define LDX4T(r0, r1, r2, r3, addr) \
    asm volatile("ldmatrix.sync.aligned.m8n8.x4.trans.shared.b16 {%0,%1,%2,%3}, [%4];" \
        : "=r"(r0), "=r"(r1), "=r"(r2), "=r"(r3) : "r"(addr))

#define CP_ASYNC16(dst, src) \
    asm volatile("cp.async.cg.shared.global [%0], [%1], 16;" :: "r"(dst), "l"(src))
#define CP_COMMIT() asm volatile("cp.async.commit_group;")
#define CP_WAIT(n)  asm volatile("cp.async.wait_group %0;" :: "n"(n))

__device__ __forceinline__ void mma_bf16(float c[4], const uint32_t a[4], const uint32_t b[2]) {
    asm volatile("mma.sync.aligned.m16n8k16.row.col.f32.bf16.bf16.f32 "
                 "{%0,%1,%2,%3}, {%4,%5,%6,%7}, {%8,%9}, {%0,%1,%2,%3};"
                 : "+f"(c[0]), "+f"(c[1]), "+f"(c[2]), "+f"(c[3])
                 : "r"(a[0]), "r"(a[1]), "r"(a[2]), "r"(a[3]), "r"(b[0]), "r"(b[1]));
}

// rne pack: {bf16(x1) : bf16(x0)}
__device__ __forceinline__ uint32_t packf(float x0, float x1) {
    uint32_t r;
    asm("cvt.rn.bf16x2.f32 %0, %1, %2;" : "=r"(r) : "f"(x1), "f"(x0));
    return r;
}
// residual pack given rne-pack ph of (x0,x1)
__device__ __forceinline__ uint32_t packlo(uint32_t ph, float x0, float x1) {
    float r0 = x0 - __uint_as_float(ph << 16);
    float r1 = x1 - __uint_as_float(ph & 0xFFFF0000u);
    return packf(r0, r1);
}

// ---------------------------------------------------------------------------
// split kernel: fp32 -> (hi bf16x2, lo bf16x2), 4 floats per thread
// ---------------------------------------------------------------------------
__global__ void split_kernel(const float4* __restrict__ src,
                             uint2* __restrict__ hi, uint2* __restrict__ lo, int n4)
{
    int i = blockIdx.x * blockDim.x + threadIdx.x;
    if (i >= n4) return;
    float4 f = src[i];
    uint32_t h0 = packf(f.x, f.y), h1 = packf(f.z, f.w);
    hi[i] = make_uint2(h0, h1);
    lo[i] = make_uint2(packlo(h0, f.x, f.y), packlo(h1, f.z, f.w));
}

// ---------------------------------------------------------------------------
// Pure-bf16 split GEMM: C[M,N] = A[M,K] * W[N,K]^T, K=2048 fixed.
// A/B pre-split hi/lo bf16. 128x128 tile, BK=32, 2-stage cp.async,
// 2 CTAs/SM (80 KB smem). smem rows: 32 bf16 = 64B + 16B pad = 80B.
// ---------------------------------------------------------------------------
constexpr int GB_ROW   = 80;
constexpr int GB_TILE  = 128 * GB_ROW;     // 10240
constexpr int GB_STAGE = 4 * GB_TILE;      // 40960 (Ahi,Alo,Bhi,Blo)
constexpr int GB_SMEM  = 2 * GB_STAGE;     // 81920

__device__ __forceinline__ void gemm_core(
    const char* Ah, const char* Al, const char* Bh, const char* Bl,
    float* C, int ldc, char* smem)
{
    const uint32_t sbase = smem_u32(smem);
    const int tid  = threadIdx.x;
    const int wid  = tid >> 5;
    const int lane = tid & 31;
    const int m0 = blockIdx.y * 128;
    const int n0 = blockIdx.x * 128;
    const int wm = wid & 1;
    const int wn = wid >> 1;
    const int lmrow = lane & 15;
    const int lmk   = (lane >> 4) * 16;

    float acc[4][4][4];
#pragma unroll
    for (int i = 0; i < 4; ++i)
#pragma unroll
        for (int j = 0; j < 4; ++j)
#pragma unroll
            for (int r = 0; r < 4; ++r) acc[i][j][r] = 0.f;

    // stage issue: 2048 x 16B chunks, 8 per thread
    auto issue = [&](int kt, int s) {
#pragma unroll
        for (int c = 0; c < 8; ++c) {
            int ch  = c * 256 + tid;
            int arr = ch >> 9;          // 0=Ah 1=Al 2=Bh 3=Bl
            int r   = (ch >> 2) & 127;
            int c16 = ch & 3;
            const char* g;
            if      (arr == 0) g = Ah + (size_t)(m0 + r) * 4096 + kt * 64 + c16 * 16;
            else if (arr == 1) g = Al + (size_t)(m0 + r) * 4096 + kt * 64 + c16 * 16;
            else if (arr == 2) g = Bh + (size_t)(n0 + r) * 4096 + kt * 64 + c16 * 16;
            else               g = Bl + (size_t)(n0 + r) * 4096 + kt * 64 + c16 * 16;
            uint32_t dst = sbase + s * GB_STAGE + arr * GB_TILE + r * GB_ROW + c16 * 16;
            CP_ASYNC16(dst, g);
        }
        CP_COMMIT();
    };

    issue(0, 0);
    issue(1, 1);

    constexpr int NT = 64;   // 2048 / 32
    for (int kt = 0; kt < NT; ++kt) {
        const int s = kt & 1;
        if (kt + 1 < NT) { CP_WAIT(1); } else { CP_WAIT(0); }
        __syncthreads();

        const uint32_t tb = sbase + s * GB_STAGE;
#pragma unroll
        for (int ks = 0; ks < 2; ++ks) {
            const int kb = ks * 32 + lmk;
            uint32_t bh[4][2], bl[4][2];
#pragma unroll
            for (int g16 = 0; g16 < 2; ++g16) {
                uint32_t r0, r1, r2, r3;
                LDX4(r0, r1, r2, r3,
                     tb + 2 * GB_TILE + (uint32_t)(wn * 32 + g16 * 16 + lmrow) * GB_ROW + kb);
                bh[g16 * 2][0] = r0; bh[g16 * 2][1] = r2;
                bh[g16 * 2 + 1][0] = r1; bh[g16 * 2 + 1][1] = r3;
                LDX4(r0, r1, r2, r3,
                     tb + 3 * GB_TILE + (uint32_t)(wn * 32 + g16 * 16 + lmrow) * GB_ROW + kb);
                bl[g16 * 2][0] = r0; bl[g16 * 2][1] = r2;
                bl[g16 * 2 + 1][0] = r1; bl[g16 * 2 + 1][1] = r3;
            }
            uint32_t af[4][4];
#pragma unroll
            for (int mt = 0; mt < 4; ++mt)
                LDX4(af[mt][0], af[mt][1], af[mt][2], af[mt][3],
                     tb + (uint32_t)(wm * 64 + mt * 16 + lmrow) * GB_ROW + kb);
#pragma unroll
            for (int mt = 0; mt < 4; ++mt)
#pragma unroll
                for (int nt = 0; nt < 4; ++nt) {
                    mma_bf16(acc[mt][nt], af[mt], bh[nt]);
                    mma_bf16(acc[mt][nt], af[mt], bl[nt]);
                }
#pragma unroll
            for (int mt = 0; mt < 4; ++mt)
                LDX4(af[mt][0], af[mt][1], af[mt][2], af[mt][3],
                     tb + GB_TILE + (uint32_t)(wm * 64 + mt * 16 + lmrow) * GB_ROW + kb);
#pragma unroll
            for (int mt = 0; mt < 4; ++mt)
#pragma unroll
                for (int nt = 0; nt < 4; ++nt)
                    mma_bf16(acc[mt][nt], af[mt], bh[nt]);
        }
        __syncthreads();
        if (kt + 2 < NT) issue(kt + 2, s);
    }

    // epilogue
    const int g = lane >> 2;
    const int t = lane & 3;
#pragma unroll
    for (int mt = 0; mt < 4; ++mt) {
#pragma unroll
        for (int nt = 0; nt < 4; ++nt) {
            int r = m0 + wm * 64 + mt * 16 + g;
            int c = n0 + wn * 32 + nt * 8 + t * 2;
            *(float2*)(C + (size_t)r * ldc + c)       = make_float2(acc[mt][nt][0], acc[mt][nt][1]);
            *(float2*)(C + (size_t)(r + 8) * ldc + c) = make_float2(acc[mt][nt][2], acc[mt][nt][3]);
        }
    }
}

__global__ void __launch_bounds__(256, 2) gemm_bf16_kernel(
    const void* Ah, const void* Al, const void* Bh, const void* Bl,
    float* C, int ldc)
{
    extern __shared__ char smem[];
    gemm_core((const char*)Ah, (const char*)Al, (const char*)Bh, (const char*)Bl,
              C, ldc, smem);
}

// merged K/V projection (blockIdx.z selects weight/output)
__global__ void __launch_bounds__(256, 2) gemm_bf16_kv_kernel(
    const void* Ah, const void* Al,
    const void* Bh0, const void* Bl0, float* C0,
    const void* Bh1, const void* Bl1, float* C1)
{
    extern __shared__ char smem[];
    const void* Bh = blockIdx.z ? Bh1 : Bh0;
    const void* Bl = blockIdx.z ? Bl1 : Bl0;
    float* C = blockIdx.z ? C1 : C0;
    gemm_core((const char*)Ah, (const char*)Al, (const char*)Bh, (const char*)Bl,
              C, 512, smem);
}

// ---------------------------------------------------------------------------
// Fused rope + hi/lo split for q,k; plain split for v.
// ---------------------------------------------------------------------------
__global__ void rope_conv_kernel(
    const float* __restrict__ q, const float* __restrict__ k, const float* __restrict__ v,
    const float* __restrict__ cosb, const float* __restrict__ sinb,
    uint32_t* __restrict__ qh, uint32_t* __restrict__ ql,
    uint32_t* __restrict__ kh, uint32_t* __restrict__ kl,
    uint32_t* __restrict__ vh, uint32_t* __restrict__ vl)
{
    const int NQr = MS * Hh * 16;     // 2097152
    const int NKr = MS * HKVv * 16;   // 524288
    const int NV  = MS * 256;         // 1048576 (pairs)
    int idx = blockIdx.x * blockDim.x + threadIdx.x;
    if (idx < NQr) {
        int j = idx & 15;
        int t = idx >> 4;             // row*32 + h
        int s = (t >> 5) & (Ss - 1);
        int d0 = 2 * j;
        const float* p = q + (size_t)t * 64;
        float x0 = p[d0], x1 = p[d0 + 1], x2 = p[d0 + 32], x3 = p[d0 + 33];
        const float* cb = cosb + s * 64;
        const float* sbn = sinb + s * 64;
        float y0 = x0 * cb[d0]      - x2 * sbn[d0];
        float y1 = x1 * cb[d0 + 1]  - x3 * sbn[d0 + 1];
        float y2 = x2 * cb[d0 + 32] + x0 * sbn[d0 + 32];
        float y3 = x3 * cb[d0 + 33] + x1 * sbn[d0 + 33];
        uint32_t h0 = packf(y0, y1);
        uint32_t h1 = packf(y2, y3);
        qh[(size_t)t * 32 + j]      = h0;
        ql[(size_t)t * 32 + j]      = packlo(h0, y0, y1);
        qh[(size_t)t * 32 + 16 + j] = h1;
        ql[(size_t)t * 32 + 16 + j] = packlo(h1, y2, y3);
    } else if (idx < NQr + NKr) {
        int i2 = idx - NQr;
        int j = i2 & 15;
        int t = i2 >> 4;              // row*8 + hkv
        int s = (t >> 3) & (Ss - 1);
        int d0 = 2 * j;
        const float* p = k + (size_t)t * 64;
        float x0 = p[d0], x1 = p[d0 + 1], x2 = p[d0 + 32], x3 = p[d0 + 33];
        const float* cb = cosb + s * 64;
        const float* sbn = sinb + s * 64;
        float y0 = x0 * cb[d0]      - x2 * sbn[d0];
        float y1 = x1 * cb[d0 + 1]  - x3 * sbn[d0 + 1];
        float y2 = x2 * cb[d0 + 32] + x0 * sbn[d0 + 32];
        float y3 = x3 * cb[d0 + 33] + x1 * sbn[d0 + 33];
        uint32_t h0 = packf(y0, y1);
        uint32_t h1 = packf(y2, y3);
        kh[(size_t)t * 32 + j]      = h0;
        kl[(size_t)t * 32 + j]      = packlo(h0, y0, y1);
        kh[(size_t)t * 32 + 16 + j] = h1;
        kl[(size_t)t * 32 + 16 + j] = packlo(h1, y2, y3);
    } else if (idx < NQr + NKr + NV) {
        int i = idx - NQr - NKr;
        float x0 = v[2 * i], x1 = v[2 * i + 1];
        uint32_t h = packf(x0, x1);
        vh[i] = h;
        vl[i] = packlo(h, x0, x1);
    }
}

// ---------------------------------------------------------------------------
// Flash attention, bf16-split mma.sync, pre-split inputs, cp.async KV pipeline.
// Block 256 thr (8 warps), Q tile 128 (16 rows/warp), KV tile 64.
// smem rows 144B (9 x 16B, conflict-free).
// ---------------------------------------------------------------------------
constexpr int AROW   = 144;
constexpr int A_QH   = 0;
constexpr int A_QL   = A_QH + 128 * AROW;      // 18432
constexpr int A_KV0  = A_QL + 128 * AROW;      // 36864
constexpr int KV_ARR = 64 * AROW;              // 9216 (KH,KL,VH,VL)
constexpr int KVSTAGE = 4 * KV_ARR;            // 36864
constexpr int A_SMEM  = A_KV0 + 2 * KVSTAGE;   // 110592

__global__ void __launch_bounds__(256, 1) attn_mma_kernel(
    const uint32_t* __restrict__ qh_g, const uint32_t* __restrict__ ql_g,
    const uint32_t* __restrict__ kh_g, const uint32_t* __restrict__ kl_g,
    const uint32_t* __restrict__ vh_g, const uint32_t* __restrict__ vl_g,
    uint32_t* __restrict__ ah_g, uint32_t* __restrict__ al_g)
{
    extern __shared__ char sm[];
    const uint32_t sb = smem_u32(sm);
    const int tid  = threadIdx.x;
    const int wid  = tid >> 5;
    const int lane = tid & 31;
    const int q0 = blockIdx.x * 128;
    const int h  = blockIdx.y;
    const int b  = blockIdx.z;
    const int hkv = h >> 2;

    const int lmrow  = lane & 15;
    const int lmk    = (lane >> 4) * 16;

    // KV stage issue: 2048 chunks of 16B, 8 per thread
    auto issue_kv = [&](int t, int s) {
#pragma unroll
        for (int c = 0; c < 8; ++c) {
            int ch  = c * 256 + tid;
            int arr = ch >> 9;          // 0=KH 1=KL 2=VH 3=VL
            int r   = (ch >> 3) & 63;
            int c16 = ch & 7;
            const uint32_t* gsrc;
            if      (arr == 0) gsrc = kh_g;
            else if (arr == 1) gsrc = kl_g;
            else if (arr == 2) gsrc = vh_g;
            else               gsrc = vl_g;
            const char* g = (const char*)gsrc
                + ((size_t)(b * Ss + t * 64 + r) * 256 + hkv * 32) * 4 + c16 * 16;
            uint32_t dst = sb + A_KV0 + s * KVSTAGE + arr * KV_ARR + r * AROW + c16 * 16;
            CP_ASYNC16(dst, g);
        }
        CP_COMMIT();
    };

    issue_kv(0, 0);

    // ---- stage Q (plain loads, once) ----
#pragma unroll
    for (int c = 0; c < 8; ++c) {
        int ch  = c * 256 + tid;
        int arr = ch >> 10;             // 0=QH 1=QL
        int r   = (ch >> 3) & 127;
        int c16 = ch & 7;
        const char* src = (const char*)(arr ? ql_g : qh_g)
            + ((size_t)(b * Ss + q0 + r) * 1024 + h * 32) * 4 + c16 * 16;
        *(uint4*)(sm + (arr ? A_QL : A_QH) + r * AROW + c16 * 16) = *(const uint4*)src;
    }
    __syncthreads();

    // ---- hoist Q fragments into registers ----
    uint32_t qfh[4][4], qfl[4][4];
#pragma unroll
    for (int kd = 0; kd < 4; ++kd) {
        LDX4(qfh[kd][0], qfh[kd][1], qfh[kd][2], qfh[kd][3],
             sb + A_QH + (uint32_t)(wid * 16 + lmrow) * AROW + kd * 32 + lmk);
        LDX4(qfl[kd][0], qfl[kd][1], qfl[kd][2], qfl[kd][3],
             sb + A_QL + (uint32_t)(wid * 16 + lmrow) * AROW + kd * 32 + lmk);
    }

    float o[8][4];
#pragma unroll
    for (int j = 0; j < 8; ++j)
#pragma unroll
        for (int r = 0; r < 4; ++r) o[j][r] = 0.f;
    float mstat[2] = {-1e30f, -1e30f};
    float lstat[2] = {0.f, 0.f};

    for (int t = 0; t < Ss / 64; ++t) {
        const int s = t & 1;
        if (t + 1 < Ss / 64) { issue_kv(t + 1, s ^ 1); CP_WAIT(1); }
        else { CP_WAIT(0); }
        __syncthreads();

        const uint32_t kvb = sb + A_KV0 + s * KVSTAGE;

        // ---- S = Q K^T (3-term split) ----
        float sreg[8][4];
#pragma unroll
        for (int j = 0; j < 8; ++j)
#pragma unroll
            for (int r = 0; r < 4; ++r) sreg[j][r] = 0.f;

#pragma unroll
        for (int kd = 0; kd < 4; ++kd) {
#pragma unroll
            for (int j16 = 0; j16 < 4; ++j16) {
                uint32_t h0, h1, h2, h3, l0, l1, l2, l3;
                LDX4(h0, h1, h2, h3,
                     kvb + 0 * KV_ARR + (uint32_t)(j16 * 16 + lmrow) * AROW + kd * 32 + lmk);
                LDX4(l0, l1, l2, l3,
                     kvb + 1 * KV_ARR + (uint32_t)(j16 * 16 + lmrow) * AROW + kd * 32 + lmk);
                uint32_t bh0[2] = {h0, h2}, bh1[2] = {h1, h3};
                uint32_t bl0[2] = {l0, l2}, bl1[2] = {l1, l3};
                mma_bf16(sreg[2 * j16],     qfh[kd], bh0);
                mma_bf16(sreg[2 * j16],     qfh[kd], bl0);
                mma_bf16(sreg[2 * j16],     qfl[kd], bh0);
                mma_bf16(sreg[2 * j16 + 1], qfh[kd], bh1);
                mma_bf16(sreg[2 * j16 + 1], qfh[kd], bl1);
                mma_bf16(sreg[2 * j16 + 1], qfl[kd], bh1);
            }
        }

        // ---- online softmax ----
#pragma unroll
        for (int hf = 0; hf < 2; ++hf) {
            float mx = -1e30f;
#pragma unroll
            for (int j = 0; j < 8; ++j) {
                sreg[j][hf * 2]     *= 0.125f;
                sreg[j][hf * 2 + 1] *= 0.125f;
                mx = fmaxf(mx, fmaxf(sreg[j][hf * 2], sreg[j][hf * 2 + 1]));
            }
            mx = fmaxf(mx, __shfl_xor_sync(0xffffffffu, mx, 1));
            mx = fmaxf(mx, __shfl_xor_sync(0xffffffffu, mx, 2));
            float mnew = fmaxf(mstat[hf], mx);
            float corr = __expf(mstat[hf] - mnew);
            float sum = 0.f;
#pragma unroll
            for (int j = 0; j < 8; ++j) {
                sreg[j][hf * 2]     = __expf(sreg[j][hf * 2] - mnew);
                sreg[j][hf * 2 + 1] = __expf(sreg[j][hf * 2 + 1] - mnew);
                sum += sreg[j][hf * 2] + sreg[j][hf * 2 + 1];
            }
            sum += __shfl_xor_sync(0xffffffffu, sum, 1);
            sum += __shfl_xor_sync(0xffffffffu, sum, 2);
            lstat[hf] = lstat[hf] * corr + sum;
            mstat[hf] = mnew;
#pragma unroll
            for (int j = 0; j < 8; ++j) {
                o[j][hf * 2]     *= corr;
                o[j][hf * 2 + 1] *= corr;
            }
        }

        // ---- O += P V (3-term split) ----
#pragma unroll
        for (int kk = 0; kk < 4; ++kk) {
            uint32_t ah[4], al[4];
            ah[0] = packf(sreg[2 * kk][0],     sreg[2 * kk][1]);
            ah[1] = packf(sreg[2 * kk][2],     sreg[2 * kk][3]);
            ah[2] = packf(sreg[2 * kk + 1][0], sreg[2 * kk + 1][1]);
            ah[3] = packf(sreg[2 * kk + 1][2], sreg[2 * kk + 1][3]);
            al[0] = packlo(ah[0], sreg[2 * kk][0],     sreg[2 * kk][1]);
            al[1] = packlo(ah[1], sreg[2 * kk][2],     sreg[2 * kk][3]);
            al[2] = packlo(ah[2], sreg[2 * kk + 1][0], sreg[2 * kk + 1][1]);
            al[3] = packlo(ah[3], sreg[2 * kk + 1][2], sreg[2 * kk + 1][3]);
#pragma unroll
            for (int j = 0; j < 4; ++j) {
                uint32_t vh0, vh1, vh2, vh3, vl0, vl1, vl2, vl3;
                LDX4T(vh0, vh1, vh2, vh3,
                      kvb + 2 * KV_ARR + (uint32_t)(kk * 16 + lmrow) * AROW + j * 32 + lmk);
                LDX4T(vl0, vl1, vl2, vl3,
                      kvb + 3 * KV_ARR + (uint32_t)(kk * 16 + lmrow) * AROW + j * 32 + lmk);
                uint32_t bh0[2] = {vh0, vh1}, bh1[2] = {vh2, vh3};
                uint32_t bl0[2] = {vl0, vl1}, bl1[2] = {vl2, vl3};
                mma_bf16(o[2 * j],     ah, bh0);
                mma_bf16(o[2 * j],     al, bh0);
                mma_bf16(o[2 * j],     ah, bl0);
                mma_bf16(o[2 * j + 1], ah, bh1);
                mma_bf16(o[2 * j + 1], al, bh1);
                mma_bf16(o[2 * j + 1], ah, bl1);
            }
        }
        __syncthreads();
    }

    // ---- epilogue: write hi/lo bf16 attn output (input to O projection) ----
    const int g  = lane >> 2;
    const int tt = lane & 3;
    const float inv0 = 1.f / lstat[0];
    const float inv1 = 1.f / lstat[1];
    const int mrow = q0 + wid * 16 + g;
    uint32_t* ah0 = ah_g + (size_t)(b * Ss + mrow) * 1024 + h * 32;
    uint32_t* al0 = al_g + (size_t)(b * Ss + mrow) * 1024 + h * 32;
    uint32_t* ah1 = ah0 + (size_t)8 * 1024;
    uint32_t* al1 = al0 + (size_t)8 * 1024;
#pragma unroll
    for (int j = 0; j < 8; ++j) {
        float y0 = o[j][0] * inv0, y1 = o[j][1] * inv0;
        uint32_t ph = packf(y0, y1);
        ah0[j * 4 + tt] = ph;
        al0[j * 4 + tt] = packlo(ph, y0, y1);
        float y2 = o[j][2] * inv1, y3 = o[j][3] * inv1;
        uint32_t ph2 = packf(y2, y3);
        ah1[j * 4 + tt] = ph2;
        al1[j * 4 + tt] = packlo(ph2, y2, y3);
    }
}

// ---------------------------------------------------------------------------
extern "C" void kernel_launch(void* const* d_in, const int* in_sizes, int n_in,
                              void* d_out, int out_size)
{
    (void)in_sizes; (void)n_in; (void)out_size;
    const float* x    = (const float*)d_in[0];
    const float* cosb = (const float*)d_in[1];
    const float* sinb = (const float*)d_in[2];
    const float* Wq   = (const float*)d_in[3];
    const float* Wk   = (const float*)d_in[4];
    const float* Wv   = (const float*)d_in[5];
    const float* Wo   = (const float*)d_in[6];
    float* out = (float*)d_out;

    void *xh, *xl, *wqh, *wql, *wkh, *wkl, *wvh, *wvl, *woh, *wol;
    void *qb, *kb, *vb, *qhp, *qlp, *khp, *klp, *vhp, *vlp, *ahp, *alp;
    cudaGetSymbolAddress(&xh, s_xh);   cudaGetSymbolAddress(&xl, s_xl);
    cudaGetSymbolAddress(&wqh, s_wqh); cudaGetSymbolAddress(&wql, s_wql);
    cudaGetSymbolAddress(&wkh, s_wkh); cudaGetSymbolAddress(&wkl, s_wkl);
    cudaGetSymbolAddress(&wvh, s_wvh); cudaGetSymbolAddress(&wvl, s_wvl);
    cudaGetSymbolAddress(&woh, s_woh); cudaGetSymbolAddress(&wol, s_wol);
    cudaGetSymbolAddress(&qb, g_q);    cudaGetSymbolAddress(&kb, g_k);
    cudaGetSymbolAddress(&vb, g_v);
    cudaGetSymbolAddress(&qhp, s_qh);  cudaGetSymbolAddress(&qlp, s_ql);
    cudaGetSymbolAddress(&khp, s_kh);  cudaGetSymbolAddress(&klp, s_kl);
    cudaGetSymbolAddress(&vhp, s_vh);  cudaGetSymbolAddress(&vlp, s_vl);
    cudaGetSymbolAddress(&ahp, s_ah);  cudaGetSymbolAddress(&alp, s_al);

    cudaFuncSetAttribute(gemm_bf16_kernel, cudaFuncAttributeMaxDynamicSharedMemorySize, GB_SMEM);
    cudaFuncSetAttribute(gemm_bf16_kv_kernel, cudaFuncAttributeMaxDynamicSharedMemorySize, GB_SMEM);
    cudaFuncSetAttribute(attn_mma_kernel, cudaFuncAttributeMaxDynamicSharedMemorySize, A_SMEM);

    // 1) pre-split x and weights
    {
        int n4;
        n4 = MS * Ee / 4;
        split_kernel<<<(n4 + 255) / 256, 256>>>((const float4*)x, (uint2*)xh, (uint2*)xl, n4);
        n4 = Ee * Ee / 4;
        split_kernel<<<(n4 + 255) / 256, 256>>>((const float4*)Wq, (uint2*)wqh, (uint2*)wql, n4);
        n4 = 512 * Ee / 4;
        split_kernel<<<(n4 + 255) / 256, 256>>>((const float4*)Wk, (uint2*)wkh, (uint2*)wkl, n4);
        split_kernel<<<(n4 + 255) / 256, 256>>>((const float4*)Wv, (uint2*)wvh, (uint2*)wvl, n4);
        n4 = Ee * Ee / 4;
        split_kernel<<<(n4 + 255) / 256, 256>>>((const float4*)Wo, (uint2*)woh, (uint2*)wol, n4);
    }

    // 2) projections
    gemm_bf16_kernel<<<dim3(16, 32), 256, GB_SMEM>>>(xh, xl, wqh, wql, (float*)qb, 2048);
    gemm_bf16_kv_kernel<<<dim3(4, 32, 2), 256, GB_SMEM>>>(
        xh, xl, wkh, wkl, (float*)kb, wvh, wvl, (float*)vb);

    // 3) rope + split q,k; split v
    {
        int total = MS * Hh * 16 + MS * HKVv * 16 + MS * 256;
        rope_conv_kernel<<<(total + 255) / 256, 256>>>(
            (const float*)qb, (const float*)kb, (const float*)vb, cosb, sinb,
            (uint32_t*)qhp, (uint32_t*)qlp, (uint32_t*)khp, (uint32_t*)klp,
            (uint32_t*)vhp, (uint32_t*)vlp);
    }

    // 4) attention
    attn_mma_kernel<<<dim3(16, 32, 2), 256, A_SMEM>>>(
        (const uint32_t*)qhp, (const uint32_t*)qlp,
        (const uint32_t*)khp, (const uint32_t*)klp,
        (const uint32_t*)vhp, (const uint32_t*)vlp,
        (uint32_t*)ahp, (uint32_t*)alp);

    // 5) output projection
    gemm_bf16_kernel<<<dim3(16, 32), 256, GB_SMEM>>>(ahp, alp, woh, wol, out, 2048);
}

// round 7
// speedup vs baseline: 1.1905x; 1.0764x over previous
#include <cuda_runtime.h>
#include <cstdint>
#include <math.h>

// Problem constants
constexpr int Bb  = 2;
constexpr int Ss  = 2048;
constexpr int Ee  = 2048;
constexpr int Hh  = 32;
constexpr int HKVv= 8;
constexpr int Dd  = 64;
constexpr int MS  = Bb * Ss;      // 4096 rows

// ---------------------------------------------------------------------------
// Scratch (no cudaMalloc). Split arrays are bf16 pairs packed in uint32.
// ---------------------------------------------------------------------------
__device__ uint32_t s_xh[MS * Ee / 2],  s_xl[MS * Ee / 2];
__device__ uint32_t s_wqh[Ee * Ee / 2], s_wql[Ee * Ee / 2];
__device__ uint32_t s_wkh[512 * Ee / 2], s_wkl[512 * Ee / 2];
__device__ uint32_t s_wvh[512 * Ee / 2], s_wvl[512 * Ee / 2];
__device__ uint32_t s_woh[Ee * Ee / 2], s_wol[Ee * Ee / 2];
__device__ float    g_q[MS * 2048];
__device__ float    g_k[MS * 512];
__device__ uint32_t s_qh[MS * 1024], s_ql[MS * 1024];
__device__ uint32_t s_kh[MS * 256],  s_kl[MS * 256];
__device__ uint32_t s_vh[MS * 256],  s_vl[MS * 256];
__device__ uint32_t s_ah[MS * 1024], s_al[MS * 1024];

// ---------------------------------------------------------------------------
// Helpers
// ---------------------------------------------------------------------------
__device__ __forceinline__ uint32_t smem_u32(const void* p) {
    uint32_t a;
    asm("{ .reg .u64 t; cvta.to.shared.u64 t, %1; cvt.u32.u64 %0, t; }" : "=r"(a) : "l"(p));
    return a;
}

#define LDX4(r0, r1, r2, r3, addr) \
    asm volatile("ldmatrix.sync.aligned.m8n8.x4.shared.b16 {%0,%1,%2,%3}, [%4];" \
        : "=r"(r0), "=r"(r1), "=r"(r2), "=r"(r3) : "r"(addr))

#define LDX4T(r0, r1, r2, r3, addr) \
    asm volatile("ldmatrix.sync.aligned.m8n8.x4.trans.shared.b16 {%0,%1,%2,%3}, [%4];" \
        : "=r"(r0), "=r"(r1), "=r"(r2), "=r"(r3) : "r"(addr))

#define CP_ASYNC16(dst, src) \
    asm volatile("cp.async.cg.shared.global [%0], [%1], 16;" :: "r"(dst), "l"(src))
#define CP_COMMIT() asm volatile("cp.async.commit_group;")
#define CP_WAIT(n)  asm volatile("cp.async.wait_group %0;" :: "n"(n))

__device__ __forceinline__ void mma_bf16(float c[4], const uint32_t a[4], const uint32_t b[2]) {
    asm volatile("mma.sync.aligned.m16n8k16.row.col.f32.bf16.bf16.f32 "
                 "{%0,%1,%2,%3}, {%4,%5,%6,%7}, {%8,%9}, {%0,%1,%2,%3};"
                 : "+f"(c[0]), "+f"(c[1]), "+f"(c[2]), "+f"(c[3])
                 : "r"(a[0]), "r"(a[1]), "r"(a[2]), "r"(a[3]), "r"(b[0]), "r"(b[1]));
}

// rne pack: {bf16(x1) : bf16(x0)}
__device__ __forceinline__ uint32_t packf(float x0, float x1) {
    uint32_t r;
    asm("cvt.rn.bf16x2.f32 %0, %1, %2;" : "=r"(r) : "f"(x1), "f"(x0));
    return r;
}
// residual pack given rne-pack ph of (x0,x1)
__device__ __forceinline__ uint32_t packlo(uint32_t ph, float x0, float x1) {
    float r0 = x0 - __uint_as_float(ph << 16);
    float r1 = x1 - __uint_as_float(ph & 0xFFFF0000u);
    return packf(r0, r1);
}

// ---------------------------------------------------------------------------
// Fused split kernel over x, Wq, Wk, Wv, Wo (one launch).
// ---------------------------------------------------------------------------
constexpr int N4_X  = MS * Ee / 4;       // 2097152
constexpr int N4_WQ = Ee * Ee / 4;       // 1048576
constexpr int N4_WK = 512 * Ee / 4;      // 262144
constexpr int N4_TOT = N4_X + N4_WQ + 2 * N4_WK + N4_WQ;

__global__ void split_all_kernel(
    const float4* __restrict__ x,  const float4* __restrict__ wq,
    const float4* __restrict__ wk, const float4* __restrict__ wv,
    const float4* __restrict__ wo,
    uint2* __restrict__ xh,  uint2* __restrict__ xl,
    uint2* __restrict__ wqh, uint2* __restrict__ wql,
    uint2* __restrict__ wkh, uint2* __restrict__ wkl,
    uint2* __restrict__ wvh, uint2* __restrict__ wvl,
    uint2* __restrict__ woh, uint2* __restrict__ wol)
{
    int i = blockIdx.x * blockDim.x + threadIdx.x;
    if (i >= N4_TOT) return;
    const float4* src; uint2* hi; uint2* lo; int j = i;
    if (j < N4_X)                   { src = x;  hi = xh;  lo = xl;  }
    else if ((j -= N4_X)  < N4_WQ)  { src = wq; hi = wqh; lo = wql; }
    else if ((j -= N4_WQ) < N4_WK)  { src = wk; hi = wkh; lo = wkl; }
    else if ((j -= N4_WK) < N4_WK)  { src = wv; hi = wvh; lo = wvl; }
    else { j -= N4_WK;                src = wo; hi = woh; lo = wol; }
    float4 f = src[j];
    uint32_t h0 = packf(f.x, f.y), h1 = packf(f.z, f.w);
    hi[j] = make_uint2(h0, h1);
    lo[j] = make_uint2(packlo(h0, f.x, f.y), packlo(h1, f.z, f.w));
}

// ---------------------------------------------------------------------------
// Pure-bf16 split GEMM, 128x128 tile, BK=32, 3-stage cp.async, 2 CTAs/SM.
// smem rows 64B (4 x 16B chunks), XOR swizzle chunk ^= (row>>1)&3 —
// conflict-free for both cp.async stores and ldmatrix reads.
// ---------------------------------------------------------------------------
constexpr int GB_TILE  = 128 * 64;         // 8192
constexpr int GB_STAGE = 4 * GB_TILE;      // 32768 (Ahi,Alo,Bhi,Blo)
constexpr int GB_SMEM  = 3 * GB_STAGE;     // 98304; x2 CTAs = 192KB/SM

__device__ __forceinline__ uint32_t swz(uint32_t row, uint32_t chunk) {
    return row * 64 + ((chunk ^ ((row >> 1) & 3)) << 4);
}

__device__ __forceinline__ void gemm_core(
    const char* Ah, const char* Al, const char* Bh, const char* Bl,
    float* C, int ldc, uint32_t* Vh, uint32_t* Vl, char* smem)
{
    const uint32_t sbase = smem_u32(smem);
    const int tid  = threadIdx.x;
    const int wid  = tid >> 5;
    const int lane = tid & 31;
    const int m0 = blockIdx.y * 128;
    const int n0 = blockIdx.x * 128;
    const int wm = wid & 1;
    const int wn = wid >> 1;
    const int lmrow = lane & 15;
    const int lmc   = lane >> 4;      // chunk parity for ldmatrix k-halves

    float acc[4][4][4];
#pragma unroll
    for (int i = 0; i < 4; ++i)
#pragma unroll
        for (int j = 0; j < 4; ++j)
#pragma unroll
            for (int r = 0; r < 4; ++r) acc[i][j][r] = 0.f;

    // stage issue: 2048 x 16B chunks, 8 per thread
    auto issue = [&](int kt, int s) {
#pragma unroll
        for (int c = 0; c < 8; ++c) {
            int ch  = c * 256 + tid;
            int arr = ch >> 9;          // 0=Ah 1=Al 2=Bh 3=Bl
            int r   = (ch >> 2) & 127;
            int c16 = ch & 3;
            const char* g;
            if      (arr == 0) g = Ah + (size_t)(m0 + r) * 4096 + kt * 64 + c16 * 16;
            else if (arr == 1) g = Al + (size_t)(m0 + r) * 4096 + kt * 64 + c16 * 16;
            else if (arr == 2) g = Bh + (size_t)(n0 + r) * 4096 + kt * 64 + c16 * 16;
            else               g = Bl + (size_t)(n0 + r) * 4096 + kt * 64 + c16 * 16;
            uint32_t dst = sbase + s * GB_STAGE + arr * GB_TILE + swz(r, c16);
            CP_ASYNC16(dst, g);
        }
        CP_COMMIT();
    };

    issue(0, 0);
    issue(1, 1);
    issue(2, 2);

    constexpr int NT = 64;   // 2048 / 32
    int s = 0;
    for (int kt = 0; kt < NT; ++kt) {
        if (kt + 3 < NT) { CP_WAIT(2); }
        else if (kt + 2 < NT) { CP_WAIT(2); }
        else if (kt + 1 < NT) { CP_WAIT(1); }
        else { CP_WAIT(0); }
        __syncthreads();

        const uint32_t tb = sbase + s * GB_STAGE;
#pragma unroll
        for (int ks = 0; ks < 2; ++ks) {
            const uint32_t kchunk = ks * 2 + lmc;
            uint32_t bh[4][2], bl[4][2];
#pragma unroll
            for (int g16 = 0; g16 < 2; ++g16) {
                uint32_t r0, r1, r2, r3;
                LDX4(r0, r1, r2, r3,
                     tb + 2 * GB_TILE + swz(wn * 32 + g16 * 16 + lmrow, kchunk));
                bh[g16 * 2][0] = r0; bh[g16 * 2][1] = r2;
                bh[g16 * 2 + 1][0] = r1; bh[g16 * 2 + 1][1] = r3;
                LDX4(r0, r1, r2, r3,
                     tb + 3 * GB_TILE + swz(wn * 32 + g16 * 16 + lmrow, kchunk));
                bl[g16 * 2][0] = r0; bl[g16 * 2][1] = r2;
                bl[g16 * 2 + 1][0] = r1; bl[g16 * 2 + 1][1] = r3;
            }
            uint32_t af[4][4];
#pragma unroll
            for (int mt = 0; mt < 4; ++mt)
                LDX4(af[mt][0], af[mt][1], af[mt][2], af[mt][3],
                     tb + swz(wm * 64 + mt * 16 + lmrow, kchunk));
#pragma unroll
            for (int mt = 0; mt < 4; ++mt)
#pragma unroll
                for (int nt = 0; nt < 4; ++nt) {
                    mma_bf16(acc[mt][nt], af[mt], bh[nt]);
                    mma_bf16(acc[mt][nt], af[mt], bl[nt]);
                }
#pragma unroll
            for (int mt = 0; mt < 4; ++mt)
                LDX4(af[mt][0], af[mt][1], af[mt][2], af[mt][3],
                     tb + GB_TILE + swz(wm * 64 + mt * 16 + lmrow, kchunk));
#pragma unroll
            for (int mt = 0; mt < 4; ++mt)
#pragma unroll
                for (int nt = 0; nt < 4; ++nt)
                    mma_bf16(acc[mt][nt], af[mt], bh[nt]);
        }
        __syncthreads();
        if (kt + 3 < NT) issue(kt + 3, s);
        s = (s == 2) ? 0 : s + 1;
    }

    // epilogue
    const int g = lane >> 2;
    const int t = lane & 3;
    if (Vh) {
        // direct hi/lo bf16 split write (V projection; ldc in pairs = 256)
#pragma unroll
        for (int mt = 0; mt < 4; ++mt) {
#pragma unroll
            for (int nt = 0; nt < 4; ++nt) {
                int r = m0 + wm * 64 + mt * 16 + g;
                int cp2 = (n0 + wn * 32 + nt * 8 + t * 2) >> 1;
                uint32_t h0 = packf(acc[mt][nt][0], acc[mt][nt][1]);
                Vh[(size_t)r * 256 + cp2] = h0;
                Vl[(size_t)r * 256 + cp2] = packlo(h0, acc[mt][nt][0], acc[mt][nt][1]);
                uint32_t h1 = packf(acc[mt][nt][2], acc[mt][nt][3]);
                Vh[(size_t)(r + 8) * 256 + cp2] = h1;
                Vl[(size_t)(r + 8) * 256 + cp2] = packlo(h1, acc[mt][nt][2], acc[mt][nt][3]);
            }
        }
    } else {
#pragma unroll
        for (int mt = 0; mt < 4; ++mt) {
#pragma unroll
            for (int nt = 0; nt < 4; ++nt) {
                int r = m0 + wm * 64 + mt * 16 + g;
                int c = n0 + wn * 32 + nt * 8 + t * 2;
                *(float2*)(C + (size_t)r * ldc + c)       = make_float2(acc[mt][nt][0], acc[mt][nt][1]);
                *(float2*)(C + (size_t)(r + 8) * ldc + c) = make_float2(acc[mt][nt][2], acc[mt][nt][3]);
            }
        }
    }
}

__global__ void __launch_bounds__(256, 2) gemm_bf16_kernel(
    const void* Ah, const void* Al, const void* Bh, const void* Bl,
    float* C, int ldc)
{
    extern __shared__ char smem[];
    gemm_core((const char*)Ah, (const char*)Al, (const char*)Bh, (const char*)Bl,
              C, ldc, nullptr, nullptr, smem);
}

// merged K/V projection: z=0 -> K (fp32 out), z=1 -> V (split bf16 out)
__global__ void __launch_bounds__(256, 2) gemm_bf16_kv_kernel(
    const void* Ah, const void* Al,
    const void* Bh0, const void* Bl0, float* C0,
    const void* Bh1, const void* Bl1, uint32_t* Vh, uint32_t* Vl)
{
    extern __shared__ char smem[];
    if (blockIdx.z == 0)
        gemm_core((const char*)Ah, (const char*)Al, (const char*)Bh0, (const char*)Bl0,
                  C0, 512, nullptr, nullptr, smem);
    else
        gemm_core((const char*)Ah, (const char*)Al, (const char*)Bh1, (const char*)Bl1,
                  nullptr, 0, Vh, Vl, smem);
}

// ---------------------------------------------------------------------------
// Fused rope + hi/lo split for q,k.
// ---------------------------------------------------------------------------
__global__ void rope_conv_kernel(
    const float* __restrict__ q, const float* __restrict__ k,
    const float* __restrict__ cosb, const float* __restrict__ sinb,
    uint32_t* __restrict__ qh, uint32_t* __restrict__ ql,
    uint32_t* __restrict__ kh, uint32_t* __restrict__ kl)
{
    const int NQr = MS * Hh * 16;     // 2097152
    const int NKr = MS * HKVv * 16;   // 524288
    int idx = blockIdx.x * blockDim.x + threadIdx.x;
    if (idx < NQr) {
        int j = idx & 15;
        int t = idx >> 4;             // row*32 + h
        int s = (t >> 5) & (Ss - 1);
        int d0 = 2 * j;
        const float* p = q + (size_t)t * 64;
        float x0 = p[d0], x1 = p[d0 + 1], x2 = p[d0 + 32], x3 = p[d0 + 33];
        const float* cb = cosb + s * 64;
        const float* sbn = sinb + s * 64;
        float y0 = x0 * cb[d0]      - x2 * sbn[d0];
        float y1 = x1 * cb[d0 + 1]  - x3 * sbn[d0 + 1];
        float y2 = x2 * cb[d0 + 32] + x0 * sbn[d0 + 32];
        float y3 = x3 * cb[d0 + 33] + x1 * sbn[d0 + 33];
        uint32_t h0 = packf(y0, y1);
        uint32_t h1 = packf(y2, y3);
        qh[(size_t)t * 32 + j]      = h0;
        ql[(size_t)t * 32 + j]      = packlo(h0, y0, y1);
        qh[(size_t)t * 32 + 16 + j] = h1;
        ql[(size_t)t * 32 + 16 + j] = packlo(h1, y2, y3);
    } else if (idx < NQr + NKr) {
        int i2 = idx - NQr;
        int j = i2 & 15;
        int t = i2 >> 4;              // row*8 + hkv
        int s = (t >> 3) & (Ss - 1);
        int d0 = 2 * j;
        const float* p = k + (size_t)t * 64;
        float x0 = p[d0], x1 = p[d0 + 1], x2 = p[d0 + 32], x3 = p[d0 + 33];
        const float* cb = cosb + s * 64;
        const float* sbn = sinb + s * 64;
        float y0 = x0 * cb[d0]      - x2 * sbn[d0];
        float y1 = x1 * cb[d0 + 1]  - x3 * sbn[d0 + 1];
        float y2 = x2 * cb[d0 + 32] + x0 * sbn[d0 + 32];
        float y3 = x3 * cb[d0 + 33] + x1 * sbn[d0 + 33];
        uint32_t h0 = packf(y0, y1);
        uint32_t h1 = packf(y2, y3);
        kh[(size_t)t * 32 + j]      = h0;
        kl[(size_t)t * 32 + j]      = packlo(h0, y0, y1);
        kh[(size_t)t * 32 + 16 + j] = h1;
        kl[(size_t)t * 32 + 16 + j] = packlo(h1, y2, y3);
    }
}

// ---------------------------------------------------------------------------
// Flash attention (unchanged from R6 — at pipe rate).
// ---------------------------------------------------------------------------
constexpr int AROW   = 144;
constexpr int A_QH   = 0;
constexpr int A_QL   = A_QH + 128 * AROW;
constexpr int A_KV0  = A_QL + 128 * AROW;
constexpr int KV_ARR = 64 * AROW;
constexpr int KVSTAGE = 4 * KV_ARR;
constexpr int A_SMEM  = A_KV0 + 2 * KVSTAGE;   // 110592

__global__ void __launch_bounds__(256, 1) attn_mma_kernel(
    const uint32_t* __restrict__ qh_g, const uint32_t* __restrict__ ql_g,
    const uint32_t* __restrict__ kh_g, const uint32_t* __restrict__ kl_g,
    const uint32_t* __restrict__ vh_g, const uint32_t* __restrict__ vl_g,
    uint32_t* __restrict__ ah_g, uint32_t* __restrict__ al_g)
{
    extern __shared__ char sm[];
    const uint32_t sb = smem_u32(sm);
    const int tid  = threadIdx.x;
    const int wid  = tid >> 5;
    const int lane = tid & 31;
    const int q0 = blockIdx.x * 128;
    const int h  = blockIdx.y;
    const int b  = blockIdx.z;
    const int hkv = h >> 2;

    const int lmrow  = lane & 15;
    const int lmk    = (lane >> 4) * 16;

    auto issue_kv = [&](int t, int s) {
#pragma unroll
        for (int c = 0; c < 8; ++c) {
            int ch  = c * 256 + tid;
            int arr = ch >> 9;          // 0=KH 1=KL 2=VH 3=VL
            int r   = (ch >> 3) & 63;
            int c16 = ch & 7;
            const uint32_t* gsrc;
            if      (arr == 0) gsrc = kh_g;
            else if (arr == 1) gsrc = kl_g;
            else if (arr == 2) gsrc = vh_g;
            else               gsrc = vl_g;
            const char* g = (const char*)gsrc
                + ((size_t)(b * Ss + t * 64 + r) * 256 + hkv * 32) * 4 + c16 * 16;
            uint32_t dst = sb + A_KV0 + s * KVSTAGE + arr * KV_ARR + r * AROW + c16 * 16;
            CP_ASYNC16(dst, g);
        }
        CP_COMMIT();
    };

    issue_kv(0, 0);

#pragma unroll
    for (int c = 0; c < 8; ++c) {
        int ch  = c * 256 + tid;
        int arr = ch >> 10;
        int r   = (ch >> 3) & 127;
        int c16 = ch & 7;
        const char* src = (const char*)(arr ? ql_g : qh_g)
            + ((size_t)(b * Ss + q0 + r) * 1024 + h * 32) * 4 + c16 * 16;
        *(uint4*)(sm + (arr ? A_QL : A_QH) + r * AROW + c16 * 16) = *(const uint4*)src;
    }
    __syncthreads();

    uint32_t qfh[4][4], qfl[4][4];
#pragma unroll
    for (int kd = 0; kd < 4; ++kd) {
        LDX4(qfh[kd][0], qfh[kd][1], qfh[kd][2], qfh[kd][3],
             sb + A_QH + (uint32_t)(wid * 16 + lmrow) * AROW + kd * 32 + lmk);
        LDX4(qfl[kd][0], qfl[kd][1], qfl[kd][2], qfl[kd][3],
             sb + A_QL + (uint32_t)(wid * 16 + lmrow) * AROW + kd * 32 + lmk);
    }

    float o[8][4];
#pragma unroll
    for (int j = 0; j < 8; ++j)
#pragma unroll
        for (int r = 0; r < 4; ++r) o[j][r] = 0.f;
    float mstat[2] = {-1e30f, -1e30f};
    float lstat[2] = {0.f, 0.f};

    for (int t = 0; t < Ss / 64; ++t) {
        const int s = t & 1;
        if (t + 1 < Ss / 64) { issue_kv(t + 1, s ^ 1); CP_WAIT(1); }
        else { CP_WAIT(0); }
        __syncthreads();

        const uint32_t kvb = sb + A_KV0 + s * KVSTAGE;

        float sreg[8][4];
#pragma unroll
        for (int j = 0; j < 8; ++j)
#pragma unroll
            for (int r = 0; r < 4; ++r) sreg[j][r] = 0.f;

#pragma unroll
        for (int kd = 0; kd < 4; ++kd) {
#pragma unroll
            for (int j16 = 0; j16 < 4; ++j16) {
                uint32_t h0, h1, h2, h3, l0, l1, l2, l3;
                LDX4(h0, h1, h2, h3,
                     kvb + 0 * KV_ARR + (uint32_t)(j16 * 16 + lmrow) * AROW + kd * 32 + lmk);
                LDX4(l0, l1, l2, l3,
                     kvb + 1 * KV_ARR + (uint32_t)(j16 * 16 + lmrow) * AROW + kd * 32 + lmk);
                uint32_t bh0[2] = {h0, h2}, bh1[2] = {h1, h3};
                uint32_t bl0[2] = {l0, l2}, bl1[2] = {l1, l3};
                mma_bf16(sreg[2 * j16],     qfh[kd], bh0);
                mma_bf16(sreg[2 * j16],     qfh[kd], bl0);
                mma_bf16(sreg[2 * j16],     qfl[kd], bh0);
                mma_bf16(sreg[2 * j16 + 1], qfh[kd], bh1);
                mma_bf16(sreg[2 * j16 + 1], qfh[kd], bl1);
                mma_bf16(sreg[2 * j16 + 1], qfl[kd], bh1);
            }
        }

#pragma unroll
        for (int hf = 0; hf < 2; ++hf) {
            float mx = -1e30f;
#pragma unroll
            for (int j = 0; j < 8; ++j) {
                sreg[j][hf * 2]     *= 0.125f;
                sreg[j][hf * 2 + 1] *= 0.125f;
                mx = fmaxf(mx, fmaxf(sreg[j][hf * 2], sreg[j][hf * 2 + 1]));
            }
            mx = fmaxf(mx, __shfl_xor_sync(0xffffffffu, mx, 1));
            mx = fmaxf(mx, __shfl_xor_sync(0xffffffffu, mx, 2));
            float mnew = fmaxf(mstat[hf], mx);
            float corr = __expf(mstat[hf] - mnew);
            float sum = 0.f;
#pragma unroll
            for (int j = 0; j < 8; ++j) {
                sreg[j][hf * 2]     = __expf(sreg[j][hf * 2] - mnew);
                sreg[j][hf * 2 + 1] = __expf(sreg[j][hf * 2 + 1] - mnew);
                sum += sreg[j][hf * 2] + sreg[j][hf * 2 + 1];
            }
            sum += __shfl_xor_sync(0xffffffffu, sum, 1);
            sum += __shfl_xor_sync(0xffffffffu, sum, 2);
            lstat[hf] = lstat[hf] * corr + sum;
            mstat[hf] = mnew;
#pragma unroll
            for (int j = 0; j < 8; ++j) {
                o[j][hf * 2]     *= corr;
                o[j][hf * 2 + 1] *= corr;
            }
        }

#pragma unroll
        for (int kk = 0; kk < 4; ++kk) {
            uint32_t ah[4], al[4];
            ah[0] = packf(sreg[2 * kk][0],     sreg[2 * kk][1]);
            ah[1] = packf(sreg[2 * kk][2],     sreg[2 * kk][3]);
            ah[2] = packf(sreg[2 * kk + 1][0], sreg[2 * kk + 1][1]);
            ah[3] = packf(sreg[2 * kk + 1][2], sreg[2 * kk + 1][3]);
            al[0] = packlo(ah[0], sreg[2 * kk][0],     sreg[2 * kk][1]);
            al[1] = packlo(ah[1], sreg[2 * kk][2],     sreg[2 * kk][3]);
            al[2] = packlo(ah[2], sreg[2 * kk + 1][0], sreg[2 * kk + 1][1]);
            al[3] = packlo(ah[3], sreg[2 * kk + 1][2], sreg[2 * kk + 1][3]);
#pragma unroll
            for (int j = 0; j < 4; ++j) {
                uint32_t vh0, vh1, vh2, vh3, vl0, vl1, vl2, vl3;
                LDX4T(vh0, vh1, vh2, vh3,
                      kvb + 2 * KV_ARR + (uint32_t)(kk * 16 + lmrow) * AROW + j * 32 + lmk);
                LDX4T(vl0, vl1, vl2, vl3,
                      kvb + 3 * KV_ARR + (uint32_t)(kk * 16 + lmrow) * AROW + j * 32 + lmk);
                uint32_t bh0[2] = {vh0, vh1}, bh1[2] = {vh2, vh3};
                uint32_t bl0[2] = {vl0, vl1}, bl1[2] = {vl2, vl3};
                mma_bf16(o[2 * j],     ah, bh0);
                mma_bf16(o[2 * j],     al, bh0);
                mma_bf16(o[2 * j],     ah, bl0);
                mma_bf16(o[2 * j + 1], ah, bh1);
                mma_bf16(o[2 * j + 1], al, bh1);
                mma_bf16(o[2 * j + 1], ah, bl1);
            }
        }
        __syncthreads();
    }

    const int g  = lane >> 2;
    const int tt = lane & 3;
    const float inv0 = 1.f / lstat[0];
    const float inv1 = 1.f / lstat[1];
    const int mrow = q0 + wid * 16 + g;
    uint32_t* ah0 = ah_g + (size_t)(b * Ss + mrow) * 1024 + h * 32;
    uint32_t* al0 = al_g + (size_t)(b * Ss + mrow) * 1024 + h * 32;
    uint32_t* ah1 = ah0 + (size_t)8 * 1024;
    uint32_t* al1 = al0 + (size_t)8 * 1024;
#pragma unroll
    for (int j = 0; j < 8; ++j) {
        float y0 = o[j][0] * inv0, y1 = o[j][1] * inv0;
        uint32_t ph = packf(y0, y1);
        ah0[j * 4 + tt] = ph;
        al0[j * 4 + tt] = packlo(ph, y0, y1);
        float y2 = o[j][2] * inv1, y3 = o[j][3] * inv1;
        uint32_t ph2 = packf(y2, y3);
        ah1[j * 4 + tt] = ph2;
        al1[j * 4 + tt] = packlo(ph2, y2, y3);
    }
}

// ---------------------------------------------------------------------------
extern "C" void kernel_launch(void* const* d_in, const int* in_sizes, int n_in,
                              void* d_out, int out_size)
{
    (void)in_sizes; (void)n_in; (void)out_size;
    const float* x    = (const float*)d_in[0];
    const float* cosb = (const float*)d_in[1];
    const float* sinb = (const float*)d_in[2];
    const float* Wq   = (const float*)d_in[3];
    const float* Wk   = (const float*)d_in[4];
    const float* Wv   = (const float*)d_in[5];
    const float* Wo   = (const float*)d_in[6];
    float* out = (float*)d_out;

    void *xh, *xl, *wqh, *wql, *wkh, *wkl, *wvh, *wvl, *woh, *wol;
    void *qb, *kb, *qhp, *qlp, *khp, *klp, *vhp, *vlp, *ahp, *alp;
    cudaGetSymbolAddress(&xh, s_xh);   cudaGetSymbolAddress(&xl, s_xl);
    cudaGetSymbolAddress(&wqh, s_wqh); cudaGetSymbolAddress(&wql, s_wql);
    cudaGetSymbolAddress(&wkh, s_wkh); cudaGetSymbolAddress(&wkl, s_wkl);
    cudaGetSymbolAddress(&wvh, s_wvh); cudaGetSymbolAddress(&wvl, s_wvl);
    cudaGetSymbolAddress(&woh, s_woh); cudaGetSymbolAddress(&wol, s_wol);
    cudaGetSymbolAddress(&qb, g_q);    cudaGetSymbolAddress(&kb, g_k);
    cudaGetSymbolAddress(&qhp, s_qh);  cudaGetSymbolAddress(&qlp, s_ql);
    cudaGetSymbolAddress(&khp, s_kh);  cudaGetSymbolAddress(&klp, s_kl);
    cudaGetSymbolAddress(&vhp, s_vh);  cudaGetSymbolAddress(&vlp, s_vl);
    cudaGetSymbolAddress(&ahp, s_ah);  cudaGetSymbolAddress(&alp, s_al);

    cudaFuncSetAttribute(gemm_bf16_kernel, cudaFuncAttributeMaxDynamicSharedMemorySize, GB_SMEM);
    cudaFuncSetAttribute(gemm_bf16_kv_kernel, cudaFuncAttributeMaxDynamicSharedMemorySize, GB_SMEM);
    cudaFuncSetAttribute(attn_mma_kernel, cudaFuncAttributeMaxDynamicSharedMemorySize, A_SMEM);

    // 1) pre-split x and all weights (one launch)
    split_all_kernel<<<(N4_TOT + 255) / 256, 256>>>(
        (const float4*)x, (const float4*)Wq, (const float4*)Wk,
        (const float4*)Wv, (const float4*)Wo,
        (uint2*)xh, (uint2*)xl, (uint2*)wqh, (uint2*)wql,
        (uint2*)wkh, (uint2*)wkl, (uint2*)wvh, (uint2*)wvl,
        (uint2*)woh, (uint2*)wol);

    // 2) projections (V writes split bf16 directly)
    gemm_bf16_kernel<<<dim3(16, 32), 256, GB_SMEM>>>(xh, xl, wqh, wql, (float*)qb, 2048);
    gemm_bf16_kv_kernel<<<dim3(4, 32, 2), 256, GB_SMEM>>>(
        xh, xl, wkh, wkl, (float*)kb,
        wvh, wvl, (uint32_t*)vhp, (uint32_t*)vlp);

    // 3) rope + split q,k
    {
        int total = MS * Hh * 16 + MS * HKVv * 16;
        rope_conv_kernel<<<(total + 255) / 256, 256>>>(
            (const float*)qb, (const float*)kb, cosb, sinb,
            (uint32_t*)qhp, (uint32_t*)qlp, (uint32_t*)khp, (uint32_t*)klp);
    }

    // 4) attention
    attn_mma_kernel<<<dim3(16, 32, 2), 256, A_SMEM>>>(
        (const uint32_t*)qhp, (const uint32_t*)qlp,
        (const uint32_t*)khp, (const uint32_t*)klp,
        (const uint32_t*)vhp, (const uint32_t*)vlp,
        (uint32_t*)ahp, (uint32_t*)alp);

    // 5) output projection
    gemm_bf16_kernel<<<dim3(16, 32), 256, GB_SMEM>>>(ahp, alp, woh, wol, out, 2048);
}

// round 8
// speedup vs baseline: 1.6353x; 1.3736x over previous
#include <cuda_runtime.h>
#include <cuda_fp16.h>
#include <cstdint>
#include <math.h>

// Problem constants
constexpr int Bb  = 2;
constexpr int Ss  = 2048;
constexpr int Ee  = 2048;
constexpr int Hh  = 32;
constexpr int HKVv= 8;
constexpr int Dd  = 64;
constexpr int MS  = Bb * Ss;      // 4096 rows

// ---------------------------------------------------------------------------
// Scratch (no cudaMalloc). Split arrays are fp16 pairs packed in uint32.
// A-side operands keep hi+lo; B-side operands keep hi only (2-term split).
// ---------------------------------------------------------------------------
__device__ uint32_t s_xh[MS * Ee / 2],  s_xl[MS * Ee / 2];
__device__ uint32_t s_wqh[Ee * Ee / 2];
__device__ uint32_t s_wkh[512 * Ee / 2];
__device__ uint32_t s_wvh[512 * Ee / 2];
__device__ uint32_t s_woh[Ee * Ee / 2];
__device__ float    g_q[MS * 2048];
__device__ float    g_k[MS * 512];
__device__ uint32_t s_qh[MS * 1024], s_ql[MS * 1024];
__device__ uint32_t s_kh[MS * 256];
__device__ uint32_t s_vh[MS * 256];
__device__ uint32_t s_ah[MS * 1024], s_al[MS * 1024];

// ---------------------------------------------------------------------------
// Helpers
// ---------------------------------------------------------------------------
__device__ __forceinline__ uint32_t smem_u32(const void* p) {
    uint32_t a;
    asm("{ .reg .u64 t; cvta.to.shared.u64 t, %1; cvt.u32.u64 %0, t; }" : "=r"(a) : "l"(p));
    return a;
}

#define LDX4(r0, r1, r2, r3, addr) \
    asm volatile("ldmatrix.sync.aligned.m8n8.x4.shared.b16 {%0,%1,%2,%3}, [%4];" \
        : "=r"(r0), "=r"(r1), "=r"(r2), "=r"(r3) : "r"(addr))

#define LDX4T(r0, r1, r2, r3, addr) \
    asm volatile("ldmatrix.sync.aligned.m8n8.x4.trans.shared.b16 {%0,%1,%2,%3}, [%4];" \
        : "=r"(r0), "=r"(r1), "=r"(r2), "=r"(r3) : "r"(addr))

#define CP_ASYNC16(dst, src) \
    asm volatile("cp.async.cg.shared.global [%0], [%1], 16;" :: "r"(dst), "l"(src))
#define CP_COMMIT() asm volatile("cp.async.commit_group;")
#define CP_WAIT(n)  asm volatile("cp.async.wait_group %0;" :: "n"(n))

__device__ __forceinline__ void mma_f16(float c[4], const uint32_t a[4], const uint32_t b[2]) {
    asm volatile("mma.sync.aligned.m16n8k16.row.col.f32.f16.f16.f32 "
                 "{%0,%1,%2,%3}, {%4,%5,%6,%7}, {%8,%9}, {%0,%1,%2,%3};"
                 : "+f"(c[0]), "+f"(c[1]), "+f"(c[2]), "+f"(c[3])
                 : "r"(a[0]), "r"(a[1]), "r"(a[2]), "r"(a[3]), "r"(b[0]), "r"(b[1]));
}

// rne pack: {fp16(x1) : fp16(x0)} (low half = x0)
__device__ __forceinline__ uint32_t packf(float x0, float x1) {
    __half2 h = __floats2half2_rn(x0, x1);
    return *reinterpret_cast<uint32_t*>(&h);
}
// residual pack given rne-pack ph of (x0,x1)
__device__ __forceinline__ uint32_t packlo(uint32_t ph, float x0, float x1) {
    __half2 h = *reinterpret_cast<__half2*>(&ph);
    return packf(x0 - __low2float(h), x1 - __high2float(h));
}

// ---------------------------------------------------------------------------
// Fused split kernel: x -> hi+lo; weights -> hi only. One launch.
// ---------------------------------------------------------------------------
constexpr int N4_X  = MS * Ee / 4;       // 2097152
constexpr int N4_WQ = Ee * Ee / 4;       // 1048576
constexpr int N4_WK = 512 * Ee / 4;      // 262144
constexpr int N4_TOT = N4_X + N4_WQ + 2 * N4_WK + N4_WQ;

__global__ void split_all_kernel(
    const float4* __restrict__ x,  const float4* __restrict__ wq,
    const float4* __restrict__ wk, const float4* __restrict__ wv,
    const float4* __restrict__ wo,
    uint2* __restrict__ xh,  uint2* __restrict__ xl,
    uint2* __restrict__ wqh, uint2* __restrict__ wkh,
    uint2* __restrict__ wvh, uint2* __restrict__ woh)
{
    int i = blockIdx.x * blockDim.x + threadIdx.x;
    if (i >= N4_TOT) return;
    const float4* src; uint2* hi; uint2* lo = nullptr; int j = i;
    if (j < N4_X)                   { src = x;  hi = xh;  lo = xl; }
    else if ((j -= N4_X)  < N4_WQ)  { src = wq; hi = wqh; }
    else if ((j -= N4_WQ) < N4_WK)  { src = wk; hi = wkh; }
    else if ((j -= N4_WK) < N4_WK)  { src = wv; hi = wvh; }
    else { j -= N4_WK;                src = wo; hi = woh; }
    float4 f = src[j];
    uint32_t h0 = packf(f.x, f.y), h1 = packf(f.z, f.w);
    hi[j] = make_uint2(h0, h1);
    if (lo) lo[j] = make_uint2(packlo(h0, f.x, f.y), packlo(h1, f.z, f.w));
}

// ---------------------------------------------------------------------------
// fp16 2-term GEMM: C = A * W^T (K=2048). Terms: Ah*Bh + Al*Bh.
// 128x128 tile, BK=32, 4-stage cp.async, 2 CTAs/SM.
// smem rows 64B, XOR swizzle chunk ^= (row>>1)&3.
// ---------------------------------------------------------------------------
constexpr int GB_TILE  = 128 * 64;         // 8192
constexpr int GB_STAGE = 3 * GB_TILE;      // 24576 (Ah, Al, Bh)
constexpr int GB_SMEM  = 4 * GB_STAGE;     // 98304; x2 CTAs = 192KB/SM

__device__ __forceinline__ uint32_t swz(uint32_t row, uint32_t chunk) {
    return row * 64 + ((chunk ^ ((row >> 1) & 3)) << 4);
}

__device__ __forceinline__ void gemm_core(
    const char* Ah, const char* Al, const char* Bh,
    float* C, int ldc, uint32_t* Vh, char* smem)
{
    const uint32_t sbase = smem_u32(smem);
    const int tid  = threadIdx.x;
    const int wid  = tid >> 5;
    const int lane = tid & 31;
    const int m0 = blockIdx.y * 128;
    const int n0 = blockIdx.x * 128;
    const int wm = wid & 1;
    const int wn = wid >> 1;
    const int lmrow = lane & 15;
    const int lmc   = lane >> 4;

    float acc[4][4][4];
#pragma unroll
    for (int i = 0; i < 4; ++i)
#pragma unroll
        for (int j = 0; j < 4; ++j)
#pragma unroll
            for (int r = 0; r < 4; ++r) acc[i][j][r] = 0.f;

    // stage issue: 1536 x 16B chunks, 6 per thread
    auto issue = [&](int kt, int s) {
#pragma unroll
        for (int c = 0; c < 6; ++c) {
            int ch  = c * 256 + tid;
            int arr = ch >> 9;          // 0=Ah 1=Al 2=Bh
            int r   = (ch >> 2) & 127;
            int c16 = ch & 3;
            const char* g;
            if      (arr == 0) g = Ah + (size_t)(m0 + r) * 4096 + kt * 64 + c16 * 16;
            else if (arr == 1) g = Al + (size_t)(m0 + r) * 4096 + kt * 64 + c16 * 16;
            else               g = Bh + (size_t)(n0 + r) * 4096 + kt * 64 + c16 * 16;
            uint32_t dst = sbase + s * GB_STAGE + arr * GB_TILE + swz(r, c16);
            CP_ASYNC16(dst, g);
        }
        CP_COMMIT();
    };

    issue(0, 0);
    issue(1, 1);
    issue(2, 2);

    constexpr int NT = 64;   // 2048 / 32
    for (int kt = 0; kt < NT; ++kt) {
        const int s = kt & 3;
        if (kt + 1 < NT) { CP_WAIT(2); } else { CP_WAIT(0); }
        __syncthreads();

        const uint32_t tb = sbase + s * GB_STAGE;
#pragma unroll
        for (int ks = 0; ks < 2; ++ks) {
            const uint32_t kchunk = ks * 2 + lmc;
            uint32_t bh[4][2];
#pragma unroll
            for (int g16 = 0; g16 < 2; ++g16) {
                uint32_t r0, r1, r2, r3;
                LDX4(r0, r1, r2, r3,
                     tb + 2 * GB_TILE + swz(wn * 32 + g16 * 16 + lmrow, kchunk));
                bh[g16 * 2][0] = r0; bh[g16 * 2][1] = r2;
                bh[g16 * 2 + 1][0] = r1; bh[g16 * 2 + 1][1] = r3;
            }
            uint32_t afh[4][4], afl[4][4];
#pragma unroll
            for (int mt = 0; mt < 4; ++mt) {
                LDX4(afh[mt][0], afh[mt][1], afh[mt][2], afh[mt][3],
                     tb + swz(wm * 64 + mt * 16 + lmrow, kchunk));
                LDX4(afl[mt][0], afl[mt][1], afl[mt][2], afl[mt][3],
                     tb + GB_TILE + swz(wm * 64 + mt * 16 + lmrow, kchunk));
            }
#pragma unroll
            for (int mt = 0; mt < 4; ++mt)
#pragma unroll
                for (int nt = 0; nt < 4; ++nt) {
                    mma_f16(acc[mt][nt], afh[mt], bh[nt]);
                    mma_f16(acc[mt][nt], afl[mt], bh[nt]);
                }
        }
        __syncthreads();
        if (kt + 3 < NT) issue(kt + 3, (kt + 3) & 3);
    }

    // epilogue
    const int g = lane >> 2;
    const int t = lane & 3;
    if (Vh) {
        // direct fp16 hi write (V projection; pair stride 256)
#pragma unroll
        for (int mt = 0; mt < 4; ++mt) {
#pragma unroll
            for (int nt = 0; nt < 4; ++nt) {
                int r = m0 + wm * 64 + mt * 16 + g;
                int cp2 = (n0 + wn * 32 + nt * 8 + t * 2) >> 1;
                Vh[(size_t)r * 256 + cp2]       = packf(acc[mt][nt][0], acc[mt][nt][1]);
                Vh[(size_t)(r + 8) * 256 + cp2] = packf(acc[mt][nt][2], acc[mt][nt][3]);
            }
        }
    } else {
#pragma unroll
        for (int mt = 0; mt < 4; ++mt) {
#pragma unroll
            for (int nt = 0; nt < 4; ++nt) {
                int r = m0 + wm * 64 + mt * 16 + g;
                int c = n0 + wn * 32 + nt * 8 + t * 2;
                *(float2*)(C + (size_t)r * ldc + c)       = make_float2(acc[mt][nt][0], acc[mt][nt][1]);
                *(float2*)(C + (size_t)(r + 8) * ldc + c) = make_float2(acc[mt][nt][2], acc[mt][nt][3]);
            }
        }
    }
}

__global__ void __launch_bounds__(256, 2) gemm_f16_kernel(
    const void* Ah, const void* Al, const void* Bh, float* C, int ldc)
{
    extern __shared__ char smem[];
    gemm_core((const char*)Ah, (const char*)Al, (const char*)Bh, C, ldc, nullptr, smem);
}

// merged K/V projection: z=0 -> K (fp32 out), z=1 -> V (fp16 hi out)
__global__ void __launch_bounds__(256, 2) gemm_f16_kv_kernel(
    const void* Ah, const void* Al,
    const void* BhK, float* CK, const void* BhV, uint32_t* Vh)
{
    extern __shared__ char smem[];
    if (blockIdx.z == 0)
        gemm_core((const char*)Ah, (const char*)Al, (const char*)BhK, CK, 512, nullptr, smem);
    else
        gemm_core((const char*)Ah, (const char*)Al, (const char*)BhV, nullptr, 0, Vh, smem);
}

// ---------------------------------------------------------------------------
// Fused rope: q -> fp16 hi+lo; k -> fp16 hi only.
// ---------------------------------------------------------------------------
__global__ void rope_conv_kernel(
    const float* __restrict__ q, const float* __restrict__ k,
    const float* __restrict__ cosb, const float* __restrict__ sinb,
    uint32_t* __restrict__ qh, uint32_t* __restrict__ ql,
    uint32_t* __restrict__ kh)
{
    const int NQr = MS * Hh * 16;
    const int NKr = MS * HKVv * 16;
    int idx = blockIdx.x * blockDim.x + threadIdx.x;
    if (idx < NQr) {
        int j = idx & 15;
        int t = idx >> 4;             // row*32 + h
        int s = (t >> 5) & (Ss - 1);
        int d0 = 2 * j;
        const float* p = q + (size_t)t * 64;
        float x0 = p[d0], x1 = p[d0 + 1], x2 = p[d0 + 32], x3 = p[d0 + 33];
        const float* cb = cosb + s * 64;
        const float* sbn = sinb + s * 64;
        float y0 = x0 * cb[d0]      - x2 * sbn[d0];
        float y1 = x1 * cb[d0 + 1]  - x3 * sbn[d0 + 1];
        float y2 = x2 * cb[d0 + 32] + x0 * sbn[d0 + 32];
        float y3 = x3 * cb[d0 + 33] + x1 * sbn[d0 + 33];
        uint32_t h0 = packf(y0, y1);
        uint32_t h1 = packf(y2, y3);
        qh[(size_t)t * 32 + j]      = h0;
        ql[(size_t)t * 32 + j]      = packlo(h0, y0, y1);
        qh[(size_t)t * 32 + 16 + j] = h1;
        ql[(size_t)t * 32 + 16 + j] = packlo(h1, y2, y3);
    } else if (idx < NQr + NKr) {
        int i2 = idx - NQr;
        int j = i2 & 15;
        int t = i2 >> 4;              // row*8 + hkv
        int s = (t >> 3) & (Ss - 1);
        int d0 = 2 * j;
        const float* p = k + (size_t)t * 64;
        float x0 = p[d0], x1 = p[d0 + 1], x2 = p[d0 + 32], x3 = p[d0 + 33];
        const float* cb = cosb + s * 64;
        const float* sbn = sinb + s * 64;
        float y0 = x0 * cb[d0]      - x2 * sbn[d0];
        float y1 = x1 * cb[d0 + 1]  - x3 * sbn[d0 + 1];
        float y2 = x2 * cb[d0 + 32] + x0 * sbn[d0 + 32];
        float y3 = x3 * cb[d0 + 33] + x1 * sbn[d0 + 33];
        kh[(size_t)t * 32 + j]      = packf(y0, y1);
        kh[(size_t)t * 32 + 16 + j] = packf(y2, y3);
    }
}

// ---------------------------------------------------------------------------
// Flash attention, fp16 2-term. K/V hi only in smem, Q hi+lo fragments in regs,
// P hi+lo packed from registers. Block 256 thr, Q tile 128, KV tile 64.
// ---------------------------------------------------------------------------
constexpr int AROW   = 144;
constexpr int A_QH   = 0;
constexpr int A_QL   = A_QH + 128 * AROW;      // 18432
constexpr int A_KV0  = A_QL + 128 * AROW;      // 36864
constexpr int KV_ARR = 64 * AROW;              // 9216 (KH, VH)
constexpr int KVSTAGE = 2 * KV_ARR;            // 18432
constexpr int A_SMEM  = A_KV0 + 2 * KVSTAGE;   // 73728

__global__ void __launch_bounds__(256, 1) attn_mma_kernel(
    const uint32_t* __restrict__ qh_g, const uint32_t* __restrict__ ql_g,
    const uint32_t* __restrict__ kh_g, const uint32_t* __restrict__ vh_g,
    uint32_t* __restrict__ ah_g, uint32_t* __restrict__ al_g)
{
    extern __shared__ char sm[];
    const uint32_t sb = smem_u32(sm);
    const int tid  = threadIdx.x;
    const int wid  = tid >> 5;
    const int lane = tid & 31;
    const int q0 = blockIdx.x * 128;
    const int h  = blockIdx.y;
    const int b  = blockIdx.z;
    const int hkv = h >> 2;

    const int lmrow  = lane & 15;
    const int lmk    = (lane >> 4) * 16;

    // KV stage issue: 1024 chunks of 16B, 4 per thread
    auto issue_kv = [&](int t, int s) {
#pragma unroll
        for (int c = 0; c < 4; ++c) {
            int ch  = c * 256 + tid;
            int arr = ch >> 9;          // 0=KH 1=VH
            int r   = (ch >> 3) & 63;
            int c16 = ch & 7;
            const uint32_t* gsrc = arr ? vh_g : kh_g;
            const char* g = (const char*)gsrc
                + ((size_t)(b * Ss + t * 64 + r) * 256 + hkv * 32) * 4 + c16 * 16;
            uint32_t dst = sb + A_KV0 + s * KVSTAGE + arr * KV_ARR + r * AROW + c16 * 16;
            CP_ASYNC16(dst, g);
        }
        CP_COMMIT();
    };

    issue_kv(0, 0);

    // stage Q hi/lo
#pragma unroll
    for (int c = 0; c < 8; ++c) {
        int ch  = c * 256 + tid;
        int arr = ch >> 10;
        int r   = (ch >> 3) & 127;
        int c16 = ch & 7;
        const char* src = (const char*)(arr ? ql_g : qh_g)
            + ((size_t)(b * Ss + q0 + r) * 1024 + h * 32) * 4 + c16 * 16;
        *(uint4*)(sm + (arr ? A_QL : A_QH) + r * AROW + c16 * 16) = *(const uint4*)src;
    }
    __syncthreads();

    uint32_t qfh[4][4], qfl[4][4];
#pragma unroll
    for (int kd = 0; kd < 4; ++kd) {
        LDX4(qfh[kd][0], qfh[kd][1], qfh[kd][2], qfh[kd][3],
             sb + A_QH + (uint32_t)(wid * 16 + lmrow) * AROW + kd * 32 + lmk);
        LDX4(qfl[kd][0], qfl[kd][1], qfl[kd][2], qfl[kd][3],
             sb + A_QL + (uint32_t)(wid * 16 + lmrow) * AROW + kd * 32 + lmk);
    }

    float o[8][4];
#pragma unroll
    for (int j = 0; j < 8; ++j)
#pragma unroll
        for (int r = 0; r < 4; ++r) o[j][r] = 0.f;
    float mstat[2] = {-1e30f, -1e30f};
    float lstat[2] = {0.f, 0.f};

    for (int t = 0; t < Ss / 64; ++t) {
        const int s = t & 1;
        if (t + 1 < Ss / 64) { issue_kv(t + 1, s ^ 1); CP_WAIT(1); }
        else { CP_WAIT(0); }
        __syncthreads();

        const uint32_t kvb = sb + A_KV0 + s * KVSTAGE;

        // ---- S = Q K^T (2-term) ----
        float sreg[8][4];
#pragma unroll
        for (int j = 0; j < 8; ++j)
#pragma unroll
            for (int r = 0; r < 4; ++r) sreg[j][r] = 0.f;

#pragma unroll
        for (int kd = 0; kd < 4; ++kd) {
#pragma unroll
            for (int j16 = 0; j16 < 4; ++j16) {
                uint32_t h0, h1, h2, h3;
                LDX4(h0, h1, h2, h3,
                     kvb + (uint32_t)(j16 * 16 + lmrow) * AROW + kd * 32 + lmk);
                uint32_t bh0[2] = {h0, h2}, bh1[2] = {h1, h3};
                mma_f16(sreg[2 * j16],     qfh[kd], bh0);
                mma_f16(sreg[2 * j16],     qfl[kd], bh0);
                mma_f16(sreg[2 * j16 + 1], qfh[kd], bh1);
                mma_f16(sreg[2 * j16 + 1], qfl[kd], bh1);
            }
        }

        // ---- online softmax ----
#pragma unroll
        for (int hf = 0; hf < 2; ++hf) {
            float mx = -1e30f;
#pragma unroll
            for (int j = 0; j < 8; ++j) {
                sreg[j][hf * 2]     *= 0.125f;
                sreg[j][hf * 2 + 1] *= 0.125f;
                mx = fmaxf(mx, fmaxf(sreg[j][hf * 2], sreg[j][hf * 2 + 1]));
            }
            mx = fmaxf(mx, __shfl_xor_sync(0xffffffffu, mx, 1));
            mx = fmaxf(mx, __shfl_xor_sync(0xffffffffu, mx, 2));
            float mnew = fmaxf(mstat[hf], mx);
            float corr = __expf(mstat[hf] - mnew);
            float sum = 0.f;
#pragma unroll
            for (int j = 0; j < 8; ++j) {
                sreg[j][hf * 2]     = __expf(sreg[j][hf * 2] - mnew);
                sreg[j][hf * 2 + 1] = __expf(sreg[j][hf * 2 + 1] - mnew);
                sum += sreg[j][hf * 2] + sreg[j][hf * 2 + 1];
            }
            sum += __shfl_xor_sync(0xffffffffu, sum, 1);
            sum += __shfl_xor_sync(0xffffffffu, sum, 2);
            lstat[hf] = lstat[hf] * corr + sum;
            mstat[hf] = mnew;
#pragma unroll
            for (int j = 0; j < 8; ++j) {
                o[j][hf * 2]     *= corr;
                o[j][hf * 2 + 1] *= corr;
            }
        }

        // ---- O += P V (2-term: Ph*Vh + Pl*Vh) ----
#pragma unroll
        for (int kk = 0; kk < 4; ++kk) {
            uint32_t ah[4], al[4];
            ah[0] = packf(sreg[2 * kk][0],     sreg[2 * kk][1]);
            ah[1] = packf(sreg[2 * kk][2],     sreg[2 * kk][3]);
            ah[2] = packf(sreg[2 * kk + 1][0], sreg[2 * kk + 1][1]);
            ah[3] = packf(sreg[2 * kk + 1][2], sreg[2 * kk + 1][3]);
            al[0] = packlo(ah[0], sreg[2 * kk][0],     sreg[2 * kk][1]);
            al[1] = packlo(ah[1], sreg[2 * kk][2],     sreg[2 * kk][3]);
            al[2] = packlo(ah[2], sreg[2 * kk + 1][0], sreg[2 * kk + 1][1]);
            al[3] = packlo(ah[3], sreg[2 * kk + 1][2], sreg[2 * kk + 1][3]);
#pragma unroll
            for (int j = 0; j < 4; ++j) {
                uint32_t vh0, vh1, vh2, vh3;
                LDX4T(vh0, vh1, vh2, vh3,
                      kvb + KV_ARR + (uint32_t)(kk * 16 + lmrow) * AROW + j * 32 + lmk);
                uint32_t bh0[2] = {vh0, vh1}, bh1[2] = {vh2, vh3};
                mma_f16(o[2 * j],     ah, bh0);
                mma_f16(o[2 * j],     al, bh0);
                mma_f16(o[2 * j + 1], ah, bh1);
                mma_f16(o[2 * j + 1], al, bh1);
            }
        }
        __syncthreads();
    }

    // epilogue: write fp16 hi+lo attn output (A-side of O projection)
    const int g  = lane >> 2;
    const int tt = lane & 3;
    const float inv0 = 1.f / lstat[0];
    const float inv1 = 1.f / lstat[1];
    const int mrow = q0 + wid * 16 + g;
    uint32_t* ah0 = ah_g + (size_t)(b * Ss + mrow) * 1024 + h * 32;
    uint32_t* al0 = al_g + (size_t)(b * Ss + mrow) * 1024 + h * 32;
    uint32_t* ah1 = ah0 + (size_t)8 * 1024;
    uint32_t* al1 = al0 + (size_t)8 * 1024;
#pragma unroll
    for (int j = 0; j < 8; ++j) {
        float y0 = o[j][0] * inv0, y1 = o[j][1] * inv0;
        uint32_t ph = packf(y0, y1);
        ah0[j * 4 + tt] = ph;
        al0[j * 4 + tt] = packlo(ph, y0, y1);
        float y2 = o[j][2] * inv1, y3 = o[j][3] * inv1;
        uint32_t ph2 = packf(y2, y3);
        ah1[j * 4 + tt] = ph2;
        al1[j * 4 + tt] = packlo(ph2, y2, y3);
    }
}

// ---------------------------------------------------------------------------
extern "C" void kernel_launch(void* const* d_in, const int* in_sizes, int n_in,
                              void* d_out, int out_size)
{
    (void)in_sizes; (void)n_in; (void)out_size;
    const float* x    = (const float*)d_in[0];
    const float* cosb = (const float*)d_in[1];
    const float* sinb = (const float*)d_in[2];
    const float* Wq   = (const float*)d_in[3];
    const float* Wk   = (const float*)d_in[4];
    const float* Wv   = (const float*)d_in[5];
    const float* Wo   = (const float*)d_in[6];
    float* out = (float*)d_out;

    void *xh, *xl, *wqh, *wkh, *wvh, *woh;
    void *qb, *kb, *qhp, *qlp, *khp, *vhp, *ahp, *alp;
    cudaGetSymbolAddress(&xh, s_xh);   cudaGetSymbolAddress(&xl, s_xl);
    cudaGetSymbolAddress(&wqh, s_wqh); cudaGetSymbolAddress(&wkh, s_wkh);
    cudaGetSymbolAddress(&wvh, s_wvh); cudaGetSymbolAddress(&woh, s_woh);
    cudaGetSymbolAddress(&qb, g_q);    cudaGetSymbolAddress(&kb, g_k);
    cudaGetSymbolAddress(&qhp, s_qh);  cudaGetSymbolAddress(&qlp, s_ql);
    cudaGetSymbolAddress(&khp, s_kh);  cudaGetSymbolAddress(&vhp, s_vh);
    cudaGetSymbolAddress(&ahp, s_ah);  cudaGetSymbolAddress(&alp, s_al);

    cudaFuncSetAttribute(gemm_f16_kernel, cudaFuncAttributeMaxDynamicSharedMemorySize, GB_SMEM);
    cudaFuncSetAttribute(gemm_f16_kv_kernel, cudaFuncAttributeMaxDynamicSharedMemorySize, GB_SMEM);
    cudaFuncSetAttribute(attn_mma_kernel, cudaFuncAttributeMaxDynamicSharedMemorySize, A_SMEM);

    // 1) pre-split x (hi+lo) and weights (hi)
    split_all_kernel<<<(N4_TOT + 255) / 256, 256>>>(
        (const float4*)x, (const float4*)Wq, (const float4*)Wk,
        (const float4*)Wv, (const float4*)Wo,
        (uint2*)xh, (uint2*)xl, (uint2*)wqh, (uint2*)wkh,
        (uint2*)wvh, (uint2*)woh);

    // 2) projections (V writes fp16 hi directly)
    gemm_f16_kernel<<<dim3(16, 32), 256, GB_SMEM>>>(xh, xl, wqh, (float*)qb, 2048);
    gemm_f16_kv_kernel<<<dim3(4, 32, 2), 256, GB_SMEM>>>(
        xh, xl, wkh, (float*)kb, wvh, (uint32_t*)vhp);

    // 3) rope: q -> hi+lo, k -> hi
    {
        int total = MS * Hh * 16 + MS * HKVv * 16;
        rope_conv_kernel<<<(total + 255) / 256, 256>>>(
            (const float*)qb, (const float*)kb, cosb, sinb,
            (uint32_t*)qhp, (uint32_t*)qlp, (uint32_t*)khp);
    }

    // 4) attention
    attn_mma_kernel<<<dim3(16, 32, 2), 256, A_SMEM>>>(
        (const uint32_t*)qhp, (const uint32_t*)qlp,
        (const uint32_t*)khp, (const uint32_t*)vhp,
        (uint32_t*)ahp, (uint32_t*)alp);

    // 5) output projection
    gemm_f16_kernel<<<dim3(16, 32), 256, GB_SMEM>>>(ahp, alp, woh, out, 2048);
}

// round 9
// speedup vs baseline: 1.6967x; 1.0376x over previous
#include <cuda_runtime.h>
#include <cuda_fp16.h>
#include <cstdint>
#include <math.h>

// Problem constants
constexpr int Bb  = 2;
constexpr int Ss  = 2048;
constexpr int Ee  = 2048;
constexpr int Hh  = 32;
constexpr int HKVv= 8;
constexpr int Dd  = 64;
constexpr int MS  = Bb * Ss;      // 4096 rows

// ---------------------------------------------------------------------------
// Scratch. fp16 pairs packed in uint32 (low half = even element).
// ---------------------------------------------------------------------------
__device__ uint32_t s_xh[MS * Ee / 2],  s_xl[MS * Ee / 2];
__device__ uint32_t s_wqh[Ee * Ee / 2];
__device__ uint32_t s_wkh[512 * Ee / 2];
__device__ uint32_t s_wvh[512 * Ee / 2];
__device__ uint32_t s_woh[Ee * Ee / 2];
__device__ uint32_t s_qh[MS * 1024], s_ql[MS * 1024];
__device__ uint32_t s_kh[MS * 256];
__device__ uint32_t s_vh[MS * 256];
__device__ uint32_t s_ah[MS * 1024], s_al[MS * 1024];

// ---------------------------------------------------------------------------
// Helpers
// ---------------------------------------------------------------------------
__device__ __forceinline__ uint32_t smem_u32(const void* p) {
    uint32_t a;
    asm("{ .reg .u64 t; cvta.to.shared.u64 t, %1; cvt.u32.u64 %0, t; }" : "=r"(a) : "l"(p));
    return a;
}

#define LDX4(r0, r1, r2, r3, addr) \
    asm volatile("ldmatrix.sync.aligned.m8n8.x4.shared.b16 {%0,%1,%2,%3}, [%4];" \
        : "=r"(r0), "=r"(r1), "=r"(r2), "=r"(r3) : "r"(addr))

#define LDX4T(r0, r1, r2, r3, addr) \
    asm volatile("ldmatrix.sync.aligned.m8n8.x4.trans.shared.b16 {%0,%1,%2,%3}, [%4];" \
        : "=r"(r0), "=r"(r1), "=r"(r2), "=r"(r3) : "r"(addr))

#define CP_ASYNC16(dst, src) \
    asm volatile("cp.async.cg.shared.global [%0], [%1], 16;" :: "r"(dst), "l"(src))
#define CP_COMMIT() asm volatile("cp.async.commit_group;")
#define CP_WAIT(n)  asm volatile("cp.async.wait_group %0;" :: "n"(n))

__device__ __forceinline__ void mma_f16(float c[4], const uint32_t a[4], const uint32_t b[2]) {
    asm volatile("mma.sync.aligned.m16n8k16.row.col.f32.f16.f16.f32 "
                 "{%0,%1,%2,%3}, {%4,%5,%6,%7}, {%8,%9}, {%0,%1,%2,%3};"
                 : "+f"(c[0]), "+f"(c[1]), "+f"(c[2]), "+f"(c[3])
                 : "r"(a[0]), "r"(a[1]), "r"(a[2]), "r"(a[3]), "r"(b[0]), "r"(b[1]));
}

__device__ __forceinline__ uint32_t packf(float x0, float x1) {
    __half2 h = __floats2half2_rn(x0, x1);
    return *reinterpret_cast<uint32_t*>(&h);
}
__device__ __forceinline__ uint32_t packlo(uint32_t ph, float x0, float x1) {
    __half2 h = *reinterpret_cast<__half2*>(&ph);
    return packf(x0 - __low2float(h), x1 - __high2float(h));
}

// ---------------------------------------------------------------------------
// Fused split kernel: x -> hi+lo; weights -> hi. One launch.
// ---------------------------------------------------------------------------
constexpr int N4_X  = MS * Ee / 4;
constexpr int N4_WQ = Ee * Ee / 4;
constexpr int N4_WK = 512 * Ee / 4;
constexpr int N4_TOT = N4_X + N4_WQ + 2 * N4_WK + N4_WQ;

__global__ void split_all_kernel(
    const float4* __restrict__ x,  const float4* __restrict__ wq,
    const float4* __restrict__ wk, const float4* __restrict__ wv,
    const float4* __restrict__ wo,
    uint2* __restrict__ xh,  uint2* __restrict__ xl,
    uint2* __restrict__ wqh, uint2* __restrict__ wkh,
    uint2* __restrict__ wvh, uint2* __restrict__ woh)
{
    int i = blockIdx.x * blockDim.x + threadIdx.x;
    if (i >= N4_TOT) return;
    const float4* src; uint2* hi; uint2* lo = nullptr; int j = i;
    if (j < N4_X)                   { src = x;  hi = xh;  lo = xl; }
    else if ((j -= N4_X)  < N4_WQ)  { src = wq; hi = wqh; }
    else if ((j -= N4_WQ) < N4_WK)  { src = wk; hi = wkh; }
    else if ((j -= N4_WK) < N4_WK)  { src = wv; hi = wvh; }
    else { j -= N4_WK;                src = wo; hi = woh; }
    float4 f = src[j];
    uint32_t h0 = packf(f.x, f.y), h1 = packf(f.z, f.w);
    hi[j] = make_uint2(h0, h1);
    if (lo) lo[j] = make_uint2(packlo(h0, f.x, f.y), packlo(h1, f.z, f.w));
}

// ---------------------------------------------------------------------------
// fp16 2-term GEMM mainloop: acc[2][8][4] (warp tile 32x64), K=2048, BK=32,
// 4-stage cp.async. smem rows 64B, XOR swizzle.
// ---------------------------------------------------------------------------
constexpr int GB_TILE  = 128 * 64;         // 8192
constexpr int GB_STAGE = 3 * GB_TILE;      // 24576 (Ah, Al, Bh)
constexpr int GB_SMEM  = 4 * GB_STAGE;     // 98304; 2 CTAs/SM

__device__ __forceinline__ uint32_t swz(uint32_t row, uint32_t chunk) {
    return row * 64 + ((chunk ^ ((row >> 1) & 3)) << 4);
}

__device__ __forceinline__ void gemm_mainloop(
    const char* Ah, const char* Al, const char* Bh,
    int m0, int n0, char* smem, float acc[2][8][4])
{
    const uint32_t sbase = smem_u32(smem);
    const int tid  = threadIdx.x;
    const int wid  = tid >> 5;
    const int lane = tid & 31;
    const int wm = wid & 3;        // 4 m-groups of 32
    const int wn = wid >> 2;       // 2 n-groups of 64
    const int lmrow = lane & 15;
    const int lmc   = lane >> 4;

#pragma unroll
    for (int i = 0; i < 2; ++i)
#pragma unroll
        for (int j = 0; j < 8; ++j)
#pragma unroll
            for (int r = 0; r < 4; ++r) acc[i][j][r] = 0.f;

    auto issue = [&](int kt, int s) {
#pragma unroll
        for (int c = 0; c < 6; ++c) {
            int ch  = c * 256 + tid;
            int arr = ch >> 9;          // 0=Ah 1=Al 2=Bh
            int r   = (ch >> 2) & 127;
            int c16 = ch & 3;
            const char* g;
            if      (arr == 0) g = Ah + (size_t)(m0 + r) * 4096 + kt * 64 + c16 * 16;
            else if (arr == 1) g = Al + (size_t)(m0 + r) * 4096 + kt * 64 + c16 * 16;
            else               g = Bh + (size_t)(n0 + r) * 4096 + kt * 64 + c16 * 16;
            uint32_t dst = sbase + s * GB_STAGE + arr * GB_TILE + swz(r, c16);
            CP_ASYNC16(dst, g);
        }
        CP_COMMIT();
    };

    issue(0, 0);
    issue(1, 1);
    issue(2, 2);

    constexpr int NT = 64;
    for (int kt = 0; kt < NT; ++kt) {
        const int s = kt & 3;
        if (kt + 1 < NT) { CP_WAIT(2); } else { CP_WAIT(0); }
        __syncthreads();

        const uint32_t tb = sbase + s * GB_STAGE;
#pragma unroll
        for (int ks = 0; ks < 2; ++ks) {
            const uint32_t kchunk = ks * 2 + lmc;
            uint32_t bh[8][2];
#pragma unroll
            for (int g16 = 0; g16 < 4; ++g16) {
                uint32_t r0, r1, r2, r3;
                LDX4(r0, r1, r2, r3,
                     tb + 2 * GB_TILE + swz(wn * 64 + g16 * 16 + lmrow, kchunk));
                bh[g16 * 2][0] = r0; bh[g16 * 2][1] = r2;
                bh[g16 * 2 + 1][0] = r1; bh[g16 * 2 + 1][1] = r3;
            }
            uint32_t afh[2][4], afl[2][4];
#pragma unroll
            for (int mt = 0; mt < 2; ++mt) {
                LDX4(afh[mt][0], afh[mt][1], afh[mt][2], afh[mt][3],
                     tb + swz(wm * 32 + mt * 16 + lmrow, kchunk));
                LDX4(afl[mt][0], afl[mt][1], afl[mt][2], afl[mt][3],
                     tb + GB_TILE + swz(wm * 32 + mt * 16 + lmrow, kchunk));
            }
#pragma unroll
            for (int mt = 0; mt < 2; ++mt)
#pragma unroll
                for (int nt = 0; nt < 8; ++nt) {
                    mma_f16(acc[mt][nt], afh[mt], bh[nt]);
                    mma_f16(acc[mt][nt], afl[mt], bh[nt]);
                }
        }
        __syncthreads();
        if (kt + 3 < NT) issue(kt + 3, (kt + 3) & 3);
    }
}

// ---------------------------------------------------------------------------
// Fused QKV projection: one launch, 768 CTAs.
//   CTA id  <512 : Q proj (rope + hi/lo fp16 epilogue)
//   id 512..639  : K proj (rope + hi fp16 epilogue)
//   id 640..767  : V proj (hi fp16 epilogue)
// ---------------------------------------------------------------------------
__global__ void __launch_bounds__(256, 2) proj_qkv_kernel(
    const void* xh_, const void* xl_,
    const void* wqh_, const void* wkh_, const void* wvh_,
    const float* __restrict__ cosb, const float* __restrict__ sinb,
    uint32_t* __restrict__ qh, uint32_t* __restrict__ ql,
    uint32_t* __restrict__ kh, uint32_t* __restrict__ vh)
{
    extern __shared__ char smem[];
    const char* xh = (const char*)xh_;
    const char* xl = (const char*)xl_;
    const int id = blockIdx.x;
    const int tid  = threadIdx.x;
    const int wid  = tid >> 5;
    const int lane = tid & 31;
    const int wm = wid & 3;
    const int wn = wid >> 2;
    const int g  = lane >> 2;
    const int tq = lane & 3;

    float acc[2][8][4];

    if (id < 512) {
        // ---- Q projection ----
        const int m0 = (id >> 4) * 128;
        const int n0 = (id & 15) * 128;
        gemm_mainloop(xh, xl, (const char*)wqh_, m0, n0, smem, acc);
        const int head = (n0 + wn * 64) >> 6;
#pragma unroll
        for (int mt = 0; mt < 2; ++mt) {
#pragma unroll
            for (int rr = 0; rr < 2; ++rr) {
                int row = m0 + wm * 32 + mt * 16 + g + rr * 8;
                int s = row & (Ss - 1);
                const float* cb  = cosb + s * 64;
                const float* sb2 = sinb + s * 64;
                uint32_t* qh_p = qh + (size_t)row * 1024 + head * 32;
                uint32_t* ql_p = ql + (size_t)row * 1024 + head * 32;
#pragma unroll
                for (int nt = 0; nt < 4; ++nt) {
                    int d = nt * 8 + tq * 2;
                    float2 c1 = *(const float2*)(cb + d);
                    float2 s1 = *(const float2*)(sb2 + d);
                    float2 c2 = *(const float2*)(cb + d + 32);
                    float2 s2 = *(const float2*)(sb2 + d + 32);
                    float x10 = acc[mt][nt][rr * 2],     x11 = acc[mt][nt][rr * 2 + 1];
                    float x20 = acc[mt][nt + 4][rr * 2], x21 = acc[mt][nt + 4][rr * 2 + 1];
                    float y0 = x10 * c1.x - x20 * s1.x;
                    float y1 = x11 * c1.y - x21 * s1.y;
                    float y2 = x20 * c2.x + x10 * s2.x;
                    float y3 = x21 * c2.y + x11 * s2.y;
                    uint32_t h0 = packf(y0, y1);
                    qh_p[nt * 4 + tq] = h0;
                    ql_p[nt * 4 + tq] = packlo(h0, y0, y1);
                    uint32_t h1 = packf(y2, y3);
                    qh_p[16 + nt * 4 + tq] = h1;
                    ql_p[16 + nt * 4 + tq] = packlo(h1, y2, y3);
                }
            }
        }
    } else if (id < 640) {
        // ---- K projection ----
        const int id2 = id - 512;
        const int m0 = (id2 >> 2) * 128;
        const int n0 = (id2 & 3) * 128;
        gemm_mainloop(xh, xl, (const char*)wkh_, m0, n0, smem, acc);
        const int head = (n0 + wn * 64) >> 6;
#pragma unroll
        for (int mt = 0; mt < 2; ++mt) {
#pragma unroll
            for (int rr = 0; rr < 2; ++rr) {
                int row = m0 + wm * 32 + mt * 16 + g + rr * 8;
                int s = row & (Ss - 1);
                const float* cb  = cosb + s * 64;
                const float* sb2 = sinb + s * 64;
                uint32_t* kh_p = kh + (size_t)row * 256 + head * 32;
#pragma unroll
                for (int nt = 0; nt < 4; ++nt) {
                    int d = nt * 8 + tq * 2;
                    float2 c1 = *(const float2*)(cb + d);
                    float2 s1 = *(const float2*)(sb2 + d);
                    float2 c2 = *(const float2*)(cb + d + 32);
                    float2 s2 = *(const float2*)(sb2 + d + 32);
                    float x10 = acc[mt][nt][rr * 2],     x11 = acc[mt][nt][rr * 2 + 1];
                    float x20 = acc[mt][nt + 4][rr * 2], x21 = acc[mt][nt + 4][rr * 2 + 1];
                    float y0 = x10 * c1.x - x20 * s1.x;
                    float y1 = x11 * c1.y - x21 * s1.y;
                    float y2 = x20 * c2.x + x10 * s2.x;
                    float y3 = x21 * c2.y + x11 * s2.y;
                    kh_p[nt * 4 + tq]      = packf(y0, y1);
                    kh_p[16 + nt * 4 + tq] = packf(y2, y3);
                }
            }
        }
    } else {
        // ---- V projection ----
        const int id2 = id - 640;
        const int m0 = (id2 >> 2) * 128;
        const int n0 = (id2 & 3) * 128;
        gemm_mainloop(xh, xl, (const char*)wvh_, m0, n0, smem, acc);
        const int cp0 = (n0 + wn * 64) >> 1;
#pragma unroll
        for (int mt = 0; mt < 2; ++mt) {
#pragma unroll
            for (int rr = 0; rr < 2; ++rr) {
                int row = m0 + wm * 32 + mt * 16 + g + rr * 8;
                uint32_t* vh_p = vh + (size_t)row * 256 + cp0;
#pragma unroll
                for (int nt = 0; nt < 8; ++nt)
                    vh_p[nt * 4 + tq] = packf(acc[mt][nt][rr * 2], acc[mt][nt][rr * 2 + 1]);
            }
        }
    }
}

// ---------------------------------------------------------------------------
// O projection: fp32 output to d_out.
// ---------------------------------------------------------------------------
__global__ void __launch_bounds__(256, 2) gemm_out_kernel(
    const void* Ah, const void* Al, const void* Bh, float* C)
{
    extern __shared__ char smem[];
    const int tid  = threadIdx.x;
    const int wid  = tid >> 5;
    const int lane = tid & 31;
    const int m0 = blockIdx.y * 128;
    const int n0 = blockIdx.x * 128;
    const int wm = wid & 3;
    const int wn = wid >> 2;
    float acc[2][8][4];
    gemm_mainloop((const char*)Ah, (const char*)Al, (const char*)Bh, m0, n0, smem, acc);
    const int g = lane >> 2;
    const int t = lane & 3;
#pragma unroll
    for (int mt = 0; mt < 2; ++mt) {
#pragma unroll
        for (int nt = 0; nt < 8; ++nt) {
            int r = m0 + wm * 32 + mt * 16 + g;
            int c = n0 + wn * 64 + nt * 8 + t * 2;
            *(float2*)(C + (size_t)r * 2048 + c)       = make_float2(acc[mt][nt][0], acc[mt][nt][1]);
            *(float2*)(C + (size_t)(r + 8) * 2048 + c) = make_float2(acc[mt][nt][2], acc[mt][nt][3]);
        }
    }
}

// ---------------------------------------------------------------------------
// Flash attention, fp16 2-term (unchanged from R8).
// ---------------------------------------------------------------------------
constexpr int AROW   = 144;
constexpr int A_QH   = 0;
constexpr int A_QL   = A_QH + 128 * AROW;
constexpr int A_KV0  = A_QL + 128 * AROW;
constexpr int KV_ARR = 64 * AROW;
constexpr int KVSTAGE = 2 * KV_ARR;
constexpr int A_SMEM  = A_KV0 + 2 * KVSTAGE;   // 73728

__global__ void __launch_bounds__(256, 1) attn_mma_kernel(
    const uint32_t* __restrict__ qh_g, const uint32_t* __restrict__ ql_g,
    const uint32_t* __restrict__ kh_g, const uint32_t* __restrict__ vh_g,
    uint32_t* __restrict__ ah_g, uint32_t* __restrict__ al_g)
{
    extern __shared__ char sm[];
    const uint32_t sb = smem_u32(sm);
    const int tid  = threadIdx.x;
    const int wid  = tid >> 5;
    const int lane = tid & 31;
    const int q0 = blockIdx.x * 128;
    const int h  = blockIdx.y;
    const int b  = blockIdx.z;
    const int hkv = h >> 2;

    const int lmrow  = lane & 15;
    const int lmk    = (lane >> 4) * 16;

    auto issue_kv = [&](int t, int s) {
#pragma unroll
        for (int c = 0; c < 4; ++c) {
            int ch  = c * 256 + tid;
            int arr = ch >> 9;
            int r   = (ch >> 3) & 63;
            int c16 = ch & 7;
            const uint32_t* gsrc = arr ? vh_g : kh_g;
            const char* g = (const char*)gsrc
                + ((size_t)(b * Ss + t * 64 + r) * 256 + hkv * 32) * 4 + c16 * 16;
            uint32_t dst = sb + A_KV0 + s * KVSTAGE + arr * KV_ARR + r * AROW + c16 * 16;
            CP_ASYNC16(dst, g);
        }
        CP_COMMIT();
    };

    issue_kv(0, 0);

#pragma unroll
    for (int c = 0; c < 8; ++c) {
        int ch  = c * 256 + tid;
        int arr = ch >> 10;
        int r   = (ch >> 3) & 127;
        int c16 = ch & 7;
        const char* src = (const char*)(arr ? ql_g : qh_g)
            + ((size_t)(b * Ss + q0 + r) * 1024 + h * 32) * 4 + c16 * 16;
        *(uint4*)(sm + (arr ? A_QL : A_QH) + r * AROW + c16 * 16) = *(const uint4*)src;
    }
    __syncthreads();

    uint32_t qfh[4][4], qfl[4][4];
#pragma unroll
    for (int kd = 0; kd < 4; ++kd) {
        LDX4(qfh[kd][0], qfh[kd][1], qfh[kd][2], qfh[kd][3],
             sb + A_QH + (uint32_t)(wid * 16 + lmrow) * AROW + kd * 32 + lmk);
        LDX4(qfl[kd][0], qfl[kd][1], qfl[kd][2], qfl[kd][3],
             sb + A_QL + (uint32_t)(wid * 16 + lmrow) * AROW + kd * 32 + lmk);
    }

    float o[8][4];
#pragma unroll
    for (int j = 0; j < 8; ++j)
#pragma unroll
        for (int r = 0; r < 4; ++r) o[j][r] = 0.f;
    float mstat[2] = {-1e30f, -1e30f};
    float lstat[2] = {0.f, 0.f};

    for (int t = 0; t < Ss / 64; ++t) {
        const int s = t & 1;
        if (t + 1 < Ss / 64) { issue_kv(t + 1, s ^ 1); CP_WAIT(1); }
        else { CP_WAIT(0); }
        __syncthreads();

        const uint32_t kvb = sb + A_KV0 + s * KVSTAGE;

        float sreg[8][4];
#pragma unroll
        for (int j = 0; j < 8; ++j)
#pragma unroll
            for (int r = 0; r < 4; ++r) sreg[j][r] = 0.f;

#pragma unroll
        for (int kd = 0; kd < 4; ++kd) {
#pragma unroll
            for (int j16 = 0; j16 < 4; ++j16) {
                uint32_t h0, h1, h2, h3;
                LDX4(h0, h1, h2, h3,
                     kvb + (uint32_t)(j16 * 16 + lmrow) * AROW + kd * 32 + lmk);
                uint32_t bh0[2] = {h0, h2}, bh1[2] = {h1, h3};
                mma_f16(sreg[2 * j16],     qfh[kd], bh0);
                mma_f16(sreg[2 * j16],     qfl[kd], bh0);
                mma_f16(sreg[2 * j16 + 1], qfh[kd], bh1);
                mma_f16(sreg[2 * j16 + 1], qfl[kd], bh1);
            }
        }

#pragma unroll
        for (int hf = 0; hf < 2; ++hf) {
            float mx = -1e30f;
#pragma unroll
            for (int j = 0; j < 8; ++j) {
                sreg[j][hf * 2]     *= 0.125f;
                sreg[j][hf * 2 + 1] *= 0.125f;
                mx = fmaxf(mx, fmaxf(sreg[j][hf * 2], sreg[j][hf * 2 + 1]));
            }
            mx = fmaxf(mx, __shfl_xor_sync(0xffffffffu, mx, 1));
            mx = fmaxf(mx, __shfl_xor_sync(0xffffffffu, mx, 2));
            float mnew = fmaxf(mstat[hf], mx);
            float corr = __expf(mstat[hf] - mnew);
            float sum = 0.f;
#pragma unroll
            for (int j = 0; j < 8; ++j) {
                sreg[j][hf * 2]     = __expf(sreg[j][hf * 2] - mnew);
                sreg[j][hf * 2 + 1] = __expf(sreg[j][hf * 2 + 1] - mnew);
                sum += sreg[j][hf * 2] + sreg[j][hf * 2 + 1];
            }
            sum += __shfl_xor_sync(0xffffffffu, sum, 1);
            sum += __shfl_xor_sync(0xffffffffu, sum, 2);
            lstat[hf] = lstat[hf] * corr + sum;
            mstat[hf] = mnew;
#pragma unroll
            for (int j = 0; j < 8; ++j) {
                o[j][hf * 2]     *= corr;
                o[j][hf * 2 + 1] *= corr;
            }
        }

#pragma unroll
        for (int kk = 0; kk < 4; ++kk) {
            uint32_t ah[4], al[4];
            ah[0] = packf(sreg[2 * kk][0],     sreg[2 * kk][1]);
            ah[1] = packf(sreg[2 * kk][2],     sreg[2 * kk][3]);
            ah[2] = packf(sreg[2 * kk + 1][0], sreg[2 * kk + 1][1]);
            ah[3] = packf(sreg[2 * kk + 1][2], sreg[2 * kk + 1][3]);
            al[0] = packlo(ah[0], sreg[2 * kk][0],     sreg[2 * kk][1]);
            al[1] = packlo(ah[1], sreg[2 * kk][2],     sreg[2 * kk][3]);
            al[2] = packlo(ah[2], sreg[2 * kk + 1][0], sreg[2 * kk + 1][1]);
            al[3] = packlo(ah[3], sreg[2 * kk + 1][2], sreg[2 * kk + 1][3]);
#pragma unroll
            for (int j = 0; j < 4; ++j) {
                uint32_t vh0, vh1, vh2, vh3;
                LDX4T(vh0, vh1, vh2, vh3,
                      kvb + KV_ARR + (uint32_t)(kk * 16 + lmrow) * AROW + j * 32 + lmk);
                uint32_t bh0[2] = {vh0, vh1}, bh1[2] = {vh2, vh3};
                mma_f16(o[2 * j],     ah, bh0);
                mma_f16(o[2 * j],     al, bh0);
                mma_f16(o[2 * j + 1], ah, bh1);
                mma_f16(o[2 * j + 1], al, bh1);
            }
        }
        __syncthreads();
    }

    const int g  = lane >> 2;
    const int tt = lane & 3;
    const float inv0 = 1.f / lstat[0];
    const float inv1 = 1.f / lstat[1];
    const int mrow = q0 + wid * 16 + g;
    uint32_t* ah0 = ah_g + (size_t)(b * Ss + mrow) * 1024 + h * 32;
    uint32_t* al0 = al_g + (size_t)(b * Ss + mrow) * 1024 + h * 32;
    uint32_t* ah1 = ah0 + (size_t)8 * 1024;
    uint32_t* al1 = al0 + (size_t)8 * 1024;
#pragma unroll
    for (int j = 0; j < 8; ++j) {
        float y0 = o[j][0] * inv0, y1 = o[j][1] * inv0;
        uint32_t ph = packf(y0, y1);
        ah0[j * 4 + tt] = ph;
        al0[j * 4 + tt] = packlo(ph, y0, y1);
        float y2 = o[j][2] * inv1, y3 = o[j][3] * inv1;
        uint32_t ph2 = packf(y2, y3);
        ah1[j * 4 + tt] = ph2;
        al1[j * 4 + tt] = packlo(ph2, y2, y3);
    }
}

// ---------------------------------------------------------------------------
extern "C" void kernel_launch(void* const* d_in, const int* in_sizes, int n_in,
                              void* d_out, int out_size)
{
    (void)in_sizes; (void)n_in; (void)out_size;
    const float* x    = (const float*)d_in[0];
    const float* cosb = (const float*)d_in[1];
    const float* sinb = (const float*)d_in[2];
    const float* Wq   = (const float*)d_in[3];
    const float* Wk   = (const float*)d_in[4];
    const float* Wv   = (const float*)d_in[5];
    const float* Wo   = (const float*)d_in[6];
    float* out = (float*)d_out;

    void *xh, *xl, *wqh, *wkh, *wvh, *woh;
    void *qhp, *qlp, *khp, *vhp, *ahp, *alp;
    cudaGetSymbolAddress(&xh, s_xh);   cudaGetSymbolAddress(&xl, s_xl);
    cudaGetSymbolAddress(&wqh, s_wqh); cudaGetSymbolAddress(&wkh, s_wkh);
    cudaGetSymbolAddress(&wvh, s_wvh); cudaGetSymbolAddress(&woh, s_woh);
    cudaGetSymbolAddress(&qhp, s_qh);  cudaGetSymbolAddress(&qlp, s_ql);
    cudaGetSymbolAddress(&khp, s_kh);  cudaGetSymbolAddress(&vhp, s_vh);
    cudaGetSymbolAddress(&ahp, s_ah);  cudaGetSymbolAddress(&alp, s_al);

    cudaFuncSetAttribute(proj_qkv_kernel, cudaFuncAttributeMaxDynamicSharedMemorySize, GB_SMEM);
    cudaFuncSetAttribute(gemm_out_kernel, cudaFuncAttributeMaxDynamicSharedMemorySize, GB_SMEM);
    cudaFuncSetAttribute(attn_mma_kernel, cudaFuncAttributeMaxDynamicSharedMemorySize, A_SMEM);

    // 1) pre-split x (hi+lo) and weights (hi)
    split_all_kernel<<<(N4_TOT + 255) / 256, 256>>>(
        (const float4*)x, (const float4*)Wq, (const float4*)Wk,
        (const float4*)Wv, (const float4*)Wo,
        (uint2*)xh, (uint2*)xl, (uint2*)wqh, (uint2*)wkh,
        (uint2*)wvh, (uint2*)woh);

    // 2) fused QKV projections with rope/split epilogues (one launch)
    proj_qkv_kernel<<<768, 256, GB_SMEM>>>(
        xh, xl, wqh, wkh, wvh, cosb, sinb,
        (uint32_t*)qhp, (uint32_t*)qlp, (uint32_t*)khp, (uint32_t*)vhp);

    // 3) attention
    attn_mma_kernel<<<dim3(16, 32, 2), 256, A_SMEM>>>(
        (const uint32_t*)qhp, (const uint32_t*)qlp,
        (const uint32_t*)khp, (const uint32_t*)vhp,
        (uint32_t*)ahp, (uint32_t*)alp);

    // 4) output projection
    gemm_out_kernel<<<dim3(16, 32), 256, GB_SMEM>>>(ahp, alp, woh, out);
}

// round 10
// speedup vs baseline: 1.7040x; 1.0043x over previous
#include <cuda_runtime.h>
#include <cuda_fp16.h>
#include <cstdint>
#include <math.h>

// Problem constants
constexpr int Bb  = 2;
constexpr int Ss  = 2048;
constexpr int Ee  = 2048;
constexpr int Hh  = 32;
constexpr int HKVv= 8;
constexpr int Dd  = 64;
constexpr int MS  = Bb * Ss;      // 4096 rows

// ---------------------------------------------------------------------------
// Scratch. fp16 pairs packed in uint32 (low half = even element).
// ---------------------------------------------------------------------------
__device__ uint32_t s_xh[MS * Ee / 2],  s_xl[MS * Ee / 2];
__device__ uint32_t s_wqh[Ee * Ee / 2];
__device__ uint32_t s_wkh[512 * Ee / 2];
__device__ uint32_t s_wvh[512 * Ee / 2];
__device__ uint32_t s_woh[Ee * Ee / 2];
__device__ uint32_t s_qh[MS * 1024], s_ql[MS * 1024];
__device__ uint32_t s_kh[MS * 256];
__device__ uint32_t s_vh[MS * 256];
__device__ uint32_t s_ah[MS * 1024], s_al[MS * 1024];

// ---------------------------------------------------------------------------
// Helpers
// ---------------------------------------------------------------------------
__device__ __forceinline__ uint32_t smem_u32(const void* p) {
    uint32_t a;
    asm("{ .reg .u64 t; cvta.to.shared.u64 t, %1; cvt.u32.u64 %0, t; }" : "=r"(a) : "l"(p));
    return a;
}

#define LDX4(r0, r1, r2, r3, addr) \
    asm volatile("ldmatrix.sync.aligned.m8n8.x4.shared.b16 {%0,%1,%2,%3}, [%4];" \
        : "=r"(r0), "=r"(r1), "=r"(r2), "=r"(r3) : "r"(addr))

#define LDX4T(r0, r1, r2, r3, addr) \
    asm volatile("ldmatrix.sync.aligned.m8n8.x4.trans.shared.b16 {%0,%1,%2,%3}, [%4];" \
        : "=r"(r0), "=r"(r1), "=r"(r2), "=r"(r3) : "r"(addr))

#define CP_ASYNC16(dst, src) \
    asm volatile("cp.async.cg.shared.global [%0], [%1], 16;" :: "r"(dst), "l"(src))
#define CP_COMMIT() asm volatile("cp.async.commit_group;")
#define CP_WAIT(n)  asm volatile("cp.async.wait_group %0;" :: "n"(n))

__device__ __forceinline__ void mma_f16(float c[4], const uint32_t a[4], const uint32_t b[2]) {
    asm volatile("mma.sync.aligned.m16n8k16.row.col.f32.f16.f16.f32 "
                 "{%0,%1,%2,%3}, {%4,%5,%6,%7}, {%8,%9}, {%0,%1,%2,%3};"
                 : "+f"(c[0]), "+f"(c[1]), "+f"(c[2]), "+f"(c[3])
                 : "r"(a[0]), "r"(a[1]), "r"(a[2]), "r"(a[3]), "r"(b[0]), "r"(b[1]));
}

__device__ __forceinline__ uint32_t packf(float x0, float x1) {
    __half2 h = __floats2half2_rn(x0, x1);
    return *reinterpret_cast<uint32_t*>(&h);
}
__device__ __forceinline__ uint32_t packlo(uint32_t ph, float x0, float x1) {
    __half2 h = *reinterpret_cast<__half2*>(&ph);
    return packf(x0 - __low2float(h), x1 - __high2float(h));
}

// ---------------------------------------------------------------------------
// Fused split kernel: x -> hi+lo; weights -> hi. One launch.
// ---------------------------------------------------------------------------
constexpr int N4_X  = MS * Ee / 4;
constexpr int N4_WQ = Ee * Ee / 4;
constexpr int N4_WK = 512 * Ee / 4;
constexpr int N4_TOT = N4_X + N4_WQ + 2 * N4_WK + N4_WQ;

__global__ void split_all_kernel(
    const float4* __restrict__ x,  const float4* __restrict__ wq,
    const float4* __restrict__ wk, const float4* __restrict__ wv,
    const float4* __restrict__ wo,
    uint2* __restrict__ xh,  uint2* __restrict__ xl,
    uint2* __restrict__ wqh, uint2* __restrict__ wkh,
    uint2* __restrict__ wvh, uint2* __restrict__ woh)
{
    int i = blockIdx.x * blockDim.x + threadIdx.x;
    if (i >= N4_TOT) return;
    const float4* src; uint2* hi; uint2* lo = nullptr; int j = i;
    if (j < N4_X)                   { src = x;  hi = xh;  lo = xl; }
    else if ((j -= N4_X)  < N4_WQ)  { src = wq; hi = wqh; }
    else if ((j -= N4_WQ) < N4_WK)  { src = wk; hi = wkh; }
    else if ((j -= N4_WK) < N4_WK)  { src = wv; hi = wvh; }
    else { j -= N4_WK;                src = wo; hi = woh; }
    float4 f = src[j];
    uint32_t h0 = packf(f.x, f.y), h1 = packf(f.z, f.w);
    hi[j] = make_uint2(h0, h1);
    if (lo) lo[j] = make_uint2(packlo(h0, f.x, f.y), packlo(h1, f.z, f.w));
}

// ---------------------------------------------------------------------------
// fp16 2-term GEMM mainloop: acc[2][8][4] (warp tile 32x64), K=2048, BK=32,
// 4-stage cp.async, ONE __syncthreads per stage (issue-after-sync).
// ---------------------------------------------------------------------------
constexpr int GB_TILE  = 128 * 64;         // 8192
constexpr int GB_STAGE = 3 * GB_TILE;      // 24576 (Ah, Al, Bh)
constexpr int GB_SMEM  = 4 * GB_STAGE;     // 98304; 2 CTAs/SM

__device__ __forceinline__ uint32_t swz(uint32_t row, uint32_t chunk) {
    return row * 64 + ((chunk ^ ((row >> 1) & 3)) << 4);
}

__device__ __forceinline__ void gemm_mainloop(
    const char* Ah, const char* Al, const char* Bh,
    int m0, int n0, char* smem, float acc[2][8][4])
{
    const uint32_t sbase = smem_u32(smem);
    const int tid  = threadIdx.x;
    const int wid  = tid >> 5;
    const int lane = tid & 31;
    const int wm = wid & 3;        // 4 m-groups of 32
    const int wn = wid >> 2;       // 2 n-groups of 64
    const int lmrow = lane & 15;
    const int lmc   = lane >> 4;

#pragma unroll
    for (int i = 0; i < 2; ++i)
#pragma unroll
        for (int j = 0; j < 8; ++j)
#pragma unroll
            for (int r = 0; r < 4; ++r) acc[i][j][r] = 0.f;

    auto issue = [&](int kt, int s) {
#pragma unroll
        for (int c = 0; c < 6; ++c) {
            int ch  = c * 256 + tid;
            int arr = ch >> 9;          // 0=Ah 1=Al 2=Bh
            int r   = (ch >> 2) & 127;
            int c16 = ch & 3;
            const char* g;
            if      (arr == 0) g = Ah + (size_t)(m0 + r) * 4096 + kt * 64 + c16 * 16;
            else if (arr == 1) g = Al + (size_t)(m0 + r) * 4096 + kt * 64 + c16 * 16;
            else               g = Bh + (size_t)(n0 + r) * 4096 + kt * 64 + c16 * 16;
            uint32_t dst = sbase + s * GB_STAGE + arr * GB_TILE + swz(r, c16);
            CP_ASYNC16(dst, g);
        }
        CP_COMMIT();
    };

    issue(0, 0);
    issue(1, 1);
    issue(2, 2);

    constexpr int NT = 64;
    for (int kt = 0; kt < NT; ++kt) {
        const int s = kt & 3;
        if (kt + 2 < NT)      { CP_WAIT(2); }
        else if (kt + 1 < NT) { CP_WAIT(1); }
        else                  { CP_WAIT(0); }
        __syncthreads();
        // safe: stage (kt+3)&3 was last read at kt-1, before this barrier
        if (kt + 3 < NT) issue(kt + 3, (kt + 3) & 3);

        const uint32_t tb = sbase + s * GB_STAGE;
#pragma unroll
        for (int ks = 0; ks < 2; ++ks) {
            const uint32_t kchunk = ks * 2 + lmc;
            uint32_t bh[8][2];
#pragma unroll
            for (int g16 = 0; g16 < 4; ++g16) {
                uint32_t r0, r1, r2, r3;
                LDX4(r0, r1, r2, r3,
                     tb + 2 * GB_TILE + swz(wn * 64 + g16 * 16 + lmrow, kchunk));
                bh[g16 * 2][0] = r0; bh[g16 * 2][1] = r2;
                bh[g16 * 2 + 1][0] = r1; bh[g16 * 2 + 1][1] = r3;
            }
            uint32_t afh[2][4], afl[2][4];
#pragma unroll
            for (int mt = 0; mt < 2; ++mt) {
                LDX4(afh[mt][0], afh[mt][1], afh[mt][2], afh[mt][3],
                     tb + swz(wm * 32 + mt * 16 + lmrow, kchunk));
                LDX4(afl[mt][0], afl[mt][1], afl[mt][2], afl[mt][3],
                     tb + GB_TILE + swz(wm * 32 + mt * 16 + lmrow, kchunk));
            }
#pragma unroll
            for (int mt = 0; mt < 2; ++mt)
#pragma unroll
                for (int nt = 0; nt < 8; ++nt) {
                    mma_f16(acc[mt][nt], afh[mt], bh[nt]);
                    mma_f16(acc[mt][nt], afl[mt], bh[nt]);
                }
        }
        // no trailing barrier: next iteration's barrier protects buffer reuse
    }
}

// ---------------------------------------------------------------------------
// Fused QKV projection: one launch, 768 CTAs.
// ---------------------------------------------------------------------------
__global__ void __launch_bounds__(256, 2) proj_qkv_kernel(
    const void* xh_, const void* xl_,
    const void* wqh_, const void* wkh_, const void* wvh_,
    const float* __restrict__ cosb, const float* __restrict__ sinb,
    uint32_t* __restrict__ qh, uint32_t* __restrict__ ql,
    uint32_t* __restrict__ kh, uint32_t* __restrict__ vh)
{
    extern __shared__ char smem[];
    const char* xh = (const char*)xh_;
    const char* xl = (const char*)xl_;
    const int id = blockIdx.x;
    const int tid  = threadIdx.x;
    const int wid  = tid >> 5;
    const int lane = tid & 31;
    const int wm = wid & 3;
    const int wn = wid >> 2;
    const int g  = lane >> 2;
    const int tq = lane & 3;

    float acc[2][8][4];

    if (id < 512) {
        // ---- Q projection ----
        const int m0 = (id >> 4) * 128;
        const int n0 = (id & 15) * 128;
        gemm_mainloop(xh, xl, (const char*)wqh_, m0, n0, smem, acc);
        const int head = (n0 + wn * 64) >> 6;
#pragma unroll
        for (int mt = 0; mt < 2; ++mt) {
#pragma unroll
            for (int rr = 0; rr < 2; ++rr) {
                int row = m0 + wm * 32 + mt * 16 + g + rr * 8;
                int s = row & (Ss - 1);
                const float* cb  = cosb + s * 64;
                const float* sb2 = sinb + s * 64;
                uint32_t* qh_p = qh + (size_t)row * 1024 + head * 32;
                uint32_t* ql_p = ql + (size_t)row * 1024 + head * 32;
#pragma unroll
                for (int nt = 0; nt < 4; ++nt) {
                    int d = nt * 8 + tq * 2;
                    float2 c1 = *(const float2*)(cb + d);
                    float2 s1 = *(const float2*)(sb2 + d);
                    float2 c2 = *(const float2*)(cb + d + 32);
                    float2 s2 = *(const float2*)(sb2 + d + 32);
                    float x10 = acc[mt][nt][rr * 2],     x11 = acc[mt][nt][rr * 2 + 1];
                    float x20 = acc[mt][nt + 4][rr * 2], x21 = acc[mt][nt + 4][rr * 2 + 1];
                    float y0 = x10 * c1.x - x20 * s1.x;
                    float y1 = x11 * c1.y - x21 * s1.y;
                    float y2 = x20 * c2.x + x10 * s2.x;
                    float y3 = x21 * c2.y + x11 * s2.y;
                    uint32_t h0 = packf(y0, y1);
                    qh_p[nt * 4 + tq] = h0;
                    ql_p[nt * 4 + tq] = packlo(h0, y0, y1);
                    uint32_t h1 = packf(y2, y3);
                    qh_p[16 + nt * 4 + tq] = h1;
                    ql_p[16 + nt * 4 + tq] = packlo(h1, y2, y3);
                }
            }
        }
    } else if (id < 640) {
        // ---- K projection ----
        const int id2 = id - 512;
        const int m0 = (id2 >> 2) * 128;
        const int n0 = (id2 & 3) * 128;
        gemm_mainloop(xh, xl, (const char*)wkh_, m0, n0, smem, acc);
        const int head = (n0 + wn * 64) >> 6;
#pragma unroll
        for (int mt = 0; mt < 2; ++mt) {
#pragma unroll
            for (int rr = 0; rr < 2; ++rr) {
                int row = m0 + wm * 32 + mt * 16 + g + rr * 8;
                int s = row & (Ss - 1);
                const float* cb  = cosb + s * 64;
                const float* sb2 = sinb + s * 64;
                uint32_t* kh_p = kh + (size_t)row * 256 + head * 32;
#pragma unroll
                for (int nt = 0; nt < 4; ++nt) {
                    int d = nt * 8 + tq * 2;
                    float2 c1 = *(const float2*)(cb + d);
                    float2 s1 = *(const float2*)(sb2 + d);
                    float2 c2 = *(const float2*)(cb + d + 32);
                    float2 s2 = *(const float2*)(sb2 + d + 32);
                    float x10 = acc[mt][nt][rr * 2],     x11 = acc[mt][nt][rr * 2 + 1];
                    float x20 = acc[mt][nt + 4][rr * 2], x21 = acc[mt][nt + 4][rr * 2 + 1];
                    float y0 = x10 * c1.x - x20 * s1.x;
                    float y1 = x11 * c1.y - x21 * s1.y;
                    float y2 = x20 * c2.x + x10 * s2.x;
                    float y3 = x21 * c2.y + x11 * s2.y;
                    kh_p[nt * 4 + tq]      = packf(y0, y1);
                    kh_p[16 + nt * 4 + tq] = packf(y2, y3);
                }
            }
        }
    } else {
        // ---- V projection ----
        const int id2 = id - 640;
        const int m0 = (id2 >> 2) * 128;
        const int n0 = (id2 & 3) * 128;
        gemm_mainloop(xh, xl, (const char*)wvh_, m0, n0, smem, acc);
        const int cp0 = (n0 + wn * 64) >> 1;
#pragma unroll
        for (int mt = 0; mt < 2; ++mt) {
#pragma unroll
            for (int rr = 0; rr < 2; ++rr) {
                int row = m0 + wm * 32 + mt * 16 + g + rr * 8;
                uint32_t* vh_p = vh + (size_t)row * 256 + cp0;
#pragma unroll
                for (int nt = 0; nt < 8; ++nt)
                    vh_p[nt * 4 + tq] = packf(acc[mt][nt][rr * 2], acc[mt][nt][rr * 2 + 1]);
            }
        }
    }
}

// ---------------------------------------------------------------------------
// O projection: fp32 output to d_out.
// ---------------------------------------------------------------------------
__global__ void __launch_bounds__(256, 2) gemm_out_kernel(
    const void* Ah, const void* Al, const void* Bh, float* C)
{
    extern __shared__ char smem[];
    const int tid  = threadIdx.x;
    const int wid  = tid >> 5;
    const int lane = tid & 31;
    const int m0 = blockIdx.y * 128;
    const int n0 = blockIdx.x * 128;
    const int wm = wid & 3;
    const int wn = wid >> 2;
    float acc[2][8][4];
    gemm_mainloop((const char*)Ah, (const char*)Al, (const char*)Bh, m0, n0, smem, acc);
    const int g = lane >> 2;
    const int t = lane & 3;
#pragma unroll
    for (int mt = 0; mt < 2; ++mt) {
#pragma unroll
        for (int nt = 0; nt < 8; ++nt) {
            int r = m0 + wm * 32 + mt * 16 + g;
            int c = n0 + wn * 64 + nt * 8 + t * 2;
            *(float2*)(C + (size_t)r * 2048 + c)       = make_float2(acc[mt][nt][0], acc[mt][nt][1]);
            *(float2*)(C + (size_t)(r + 8) * 2048 + c) = make_float2(acc[mt][nt][2], acc[mt][nt][3]);
        }
    }
}

// ---------------------------------------------------------------------------
// Flash attention, fp16 2-term. 3-stage KV cp.async pipeline,
// single __syncthreads per tile (issue-after-sync).
// ---------------------------------------------------------------------------
constexpr int AROW   = 144;
constexpr int A_QH   = 0;
constexpr int A_QL   = A_QH + 128 * AROW;
constexpr int A_KV0  = A_QL + 128 * AROW;      // 36864
constexpr int KV_ARR = 64 * AROW;              // 9216 (KH, VH)
constexpr int KVSTAGE = 2 * KV_ARR;            // 18432
constexpr int A_SMEM  = A_KV0 + 3 * KVSTAGE;   // 92160

__global__ void __launch_bounds__(256, 1) attn_mma_kernel(
    const uint32_t* __restrict__ qh_g, const uint32_t* __restrict__ ql_g,
    const uint32_t* __restrict__ kh_g, const uint32_t* __restrict__ vh_g,
    uint32_t* __restrict__ ah_g, uint32_t* __restrict__ al_g)
{
    extern __shared__ char sm[];
    const uint32_t sb = smem_u32(sm);
    const int tid  = threadIdx.x;
    const int wid  = tid >> 5;
    const int lane = tid & 31;
    const int q0 = blockIdx.x * 128;
    const int h  = blockIdx.y;
    const int b  = blockIdx.z;
    const int hkv = h >> 2;

    const int lmrow  = lane & 15;
    const int lmk    = (lane >> 4) * 16;

    auto issue_kv = [&](int t, int s) {
#pragma unroll
        for (int c = 0; c < 4; ++c) {
            int ch  = c * 256 + tid;
            int arr = ch >> 9;
            int r   = (ch >> 3) & 63;
            int c16 = ch & 7;
            const uint32_t* gsrc = arr ? vh_g : kh_g;
            const char* g = (const char*)gsrc
                + ((size_t)(b * Ss + t * 64 + r) * 256 + hkv * 32) * 4 + c16 * 16;
            uint32_t dst = sb + A_KV0 + s * KVSTAGE + arr * KV_ARR + r * AROW + c16 * 16;
            CP_ASYNC16(dst, g);
        }
        CP_COMMIT();
    };

    issue_kv(0, 0);
    issue_kv(1, 1);

    // stage Q hi/lo
#pragma unroll
    for (int c = 0; c < 8; ++c) {
        int ch  = c * 256 + tid;
        int arr = ch >> 10;
        int r   = (ch >> 3) & 127;
        int c16 = ch & 7;
        const char* src = (const char*)(arr ? ql_g : qh_g)
            + ((size_t)(b * Ss + q0 + r) * 1024 + h * 32) * 4 + c16 * 16;
        *(uint4*)(sm + (arr ? A_QL : A_QH) + r * AROW + c16 * 16) = *(const uint4*)src;
    }
    __syncthreads();

    uint32_t qfh[4][4], qfl[4][4];
#pragma unroll
    for (int kd = 0; kd < 4; ++kd) {
        LDX4(qfh[kd][0], qfh[kd][1], qfh[kd][2], qfh[kd][3],
             sb + A_QH + (uint32_t)(wid * 16 + lmrow) * AROW + kd * 32 + lmk);
        LDX4(qfl[kd][0], qfl[kd][1], qfl[kd][2], qfl[kd][3],
             sb + A_QL + (uint32_t)(wid * 16 + lmrow) * AROW + kd * 32 + lmk);
    }

    float o[8][4];
#pragma unroll
    for (int j = 0; j < 8; ++j)
#pragma unroll
        for (int r = 0; r < 4; ++r) o[j][r] = 0.f;
    float mstat[2] = {-1e30f, -1e30f};
    float lstat[2] = {0.f, 0.f};

    constexpr int NTT = Ss / 64;   // 32
    int s3 = 0;                    // stage index t % 3
    for (int t = 0; t < NTT; ++t) {
        if (t + 1 < NTT) { CP_WAIT(1); } else { CP_WAIT(0); }
        __syncthreads();
        // safe: stage (t+2)%3 = (t-1)%3 was last read at t-1, before this barrier
        if (t + 2 < NTT) {
            int sn = s3 + 2; if (sn >= 3) sn -= 3;
            issue_kv(t + 2, sn);
        }

        const uint32_t kvb = sb + A_KV0 + s3 * KVSTAGE;

        // ---- S = Q K^T (2-term) ----
        float sreg[8][4];
#pragma unroll
        for (int j = 0; j < 8; ++j)
#pragma unroll
            for (int r = 0; r < 4; ++r) sreg[j][r] = 0.f;

#pragma unroll
        for (int kd = 0; kd < 4; ++kd) {
#pragma unroll
            for (int j16 = 0; j16 < 4; ++j16) {
                uint32_t h0, h1, h2, h3;
                LDX4(h0, h1, h2, h3,
                     kvb + (uint32_t)(j16 * 16 + lmrow) * AROW + kd * 32 + lmk);
                uint32_t bh0[2] = {h0, h2}, bh1[2] = {h1, h3};
                mma_f16(sreg[2 * j16],     qfh[kd], bh0);
                mma_f16(sreg[2 * j16],     qfl[kd], bh0);
                mma_f16(sreg[2 * j16 + 1], qfh[kd], bh1);
                mma_f16(sreg[2 * j16 + 1], qfl[kd], bh1);
            }
        }

        // ---- online softmax ----
#pragma unroll
        for (int hf = 0; hf < 2; ++hf) {
            float mx = -1e30f;
#pragma unroll
            for (int j = 0; j < 8; ++j) {
                sreg[j][hf * 2]     *= 0.125f;
                sreg[j][hf * 2 + 1] *= 0.125f;
                mx = fmaxf(mx, fmaxf(sreg[j][hf * 2], sreg[j][hf * 2 + 1]));
            }
            mx = fmaxf(mx, __shfl_xor_sync(0xffffffffu, mx, 1));
            mx = fmaxf(mx, __shfl_xor_sync(0xffffffffu, mx, 2));
            float mnew = fmaxf(mstat[hf], mx);
            float corr = __expf(mstat[hf] - mnew);
            float sum = 0.f;
#pragma unroll
            for (int j = 0; j < 8; ++j) {
                sreg[j][hf * 2]     = __expf(sreg[j][hf * 2] - mnew);
                sreg[j][hf * 2 + 1] = __expf(sreg[j][hf * 2 + 1] - mnew);
                sum += sreg[j][hf * 2] + sreg[j][hf * 2 + 1];
            }
            sum += __shfl_xor_sync(0xffffffffu, sum, 1);
            sum += __shfl_xor_sync(0xffffffffu, sum, 2);
            lstat[hf] = lstat[hf] * corr + sum;
            mstat[hf] = mnew;
#pragma unroll
            for (int j = 0; j < 8; ++j) {
                o[j][hf * 2]     *= corr;
                o[j][hf * 2 + 1] *= corr;
            }
        }

        // ---- O += P V (2-term) ----
#pragma unroll
        for (int kk = 0; kk < 4; ++kk) {
            uint32_t ah[4], al[4];
            ah[0] = packf(sreg[2 * kk][0],     sreg[2 * kk][1]);
            ah[1] = packf(sreg[2 * kk][2],     sreg[2 * kk][3]);
            ah[2] = packf(sreg[2 * kk + 1][0], sreg[2 * kk + 1][1]);
            ah[3] = packf(sreg[2 * kk + 1][2], sreg[2 * kk + 1][3]);
            al[0] = packlo(ah[0], sreg[2 * kk][0],     sreg[2 * kk][1]);
            al[1] = packlo(ah[1], sreg[2 * kk][2],     sreg[2 * kk][3]);
            al[2] = packlo(ah[2], sreg[2 * kk + 1][0], sreg[2 * kk + 1][1]);
            al[3] = packlo(ah[3], sreg[2 * kk + 1][2], sreg[2 * kk + 1][3]);
#pragma unroll
            for (int j = 0; j < 4; ++j) {
                uint32_t vh0, vh1, vh2, vh3;
                LDX4T(vh0, vh1, vh2, vh3,
                      kvb + KV_ARR + (uint32_t)(kk * 16 + lmrow) * AROW + j * 32 + lmk);
                uint32_t bh0[2] = {vh0, vh1}, bh1[2] = {vh2, vh3};
                mma_f16(o[2 * j],     ah, bh0);
                mma_f16(o[2 * j],     al, bh0);
                mma_f16(o[2 * j + 1], ah, bh1);
                mma_f16(o[2 * j + 1], al, bh1);
            }
        }
        // no trailing barrier
        if (++s3 == 3) s3 = 0;
    }

    const int g  = lane >> 2;
    const int tt = lane & 3;
    const float inv0 = 1.f / lstat[0];
    const float inv1 = 1.f / lstat[1];
    const int mrow = q0 + wid * 16 + g;
    uint32_t* ah0 = ah_g + (size_t)(b * Ss + mrow) * 1024 + h * 32;
    uint32_t* al0 = al_g + (size_t)(b * Ss + mrow) * 1024 + h * 32;
    uint32_t* ah1 = ah0 + (size_t)8 * 1024;
    uint32_t* al1 = al0 + (size_t)8 * 1024;
#pragma unroll
    for (int j = 0; j < 8; ++j) {
        float y0 = o[j][0] * inv0, y1 = o[j][1] * inv0;
        uint32_t ph = packf(y0, y1);
        ah0[j * 4 + tt] = ph;
        al0[j * 4 + tt] = packlo(ph, y0, y1);
        float y2 = o[j][2] * inv1, y3 = o[j][3] * inv1;
        uint32_t ph2 = packf(y2, y3);
        ah1[j * 4 + tt] = ph2;
        al1[j * 4 + tt] = packlo(ph2, y2, y3);
    }
}

// ---------------------------------------------------------------------------
extern "C" void kernel_launch(void* const* d_in, const int* in_sizes, int n_in,
                              void* d_out, int out_size)
{
    (void)in_sizes; (void)n_in; (void)out_size;
    const float* x    = (const float*)d_in[0];
    const float* cosb = (const float*)d_in[1];
    const float* sinb = (const float*)d_in[2];
    const float* Wq   = (const float*)d_in[3];
    const float* Wk   = (const float*)d_in[4];
    const float* Wv   = (const float*)d_in[5];
    const float* Wo   = (const float*)d_in[6];
    float* out = (float*)d_out;

    void *xh, *xl, *wqh, *wkh, *wvh, *woh;
    void *qhp, *qlp, *khp, *vhp, *ahp, *alp;
    cudaGetSymbolAddress(&xh, s_xh);   cudaGetSymbolAddress(&xl, s_xl);
    cudaGetSymbolAddress(&wqh, s_wqh); cudaGetSymbolAddress(&wkh, s_wkh);
    cudaGetSymbolAddress(&wvh, s_wvh); cudaGetSymbolAddress(&woh, s_woh);
    cudaGetSymbolAddress(&qhp, s_qh);  cudaGetSymbolAddress(&qlp, s_ql);
    cudaGetSymbolAddress(&khp, s_kh);  cudaGetSymbolAddress(&vhp, s_vh);
    cudaGetSymbolAddress(&ahp, s_ah);  cudaGetSymbolAddress(&alp, s_al);

    cudaFuncSetAttribute(proj_qkv_kernel, cudaFuncAttributeMaxDynamicSharedMemorySize, GB_SMEM);
    cudaFuncSetAttribute(gemm_out_kernel, cudaFuncAttributeMaxDynamicSharedMemorySize, GB_SMEM);
    cudaFuncSetAttribute(attn_mma_kernel, cudaFuncAttributeMaxDynamicSharedMemorySize, A_SMEM);

    // 1) pre-split x (hi+lo) and weights (hi)
    split_all_kernel<<<(N4_TOT + 255) / 256, 256>>>(
        (const float4*)x, (const float4*)Wq, (const float4*)Wk,
        (const float4*)Wv, (const float4*)Wo,
        (uint2*)xh, (uint2*)xl, (uint2*)wqh, (uint2*)wkh,
        (uint2*)wvh, (uint2*)woh);

    // 2) fused QKV projections with rope/split epilogues (one launch)
    proj_qkv_kernel<<<768, 256, GB_SMEM>>>(
        xh, xl, wqh, wkh, wvh, cosb, sinb,
        (uint32_t*)qhp, (uint32_t*)qlp, (uint32_t*)khp, (uint32_t*)vhp);

    // 3) attention
    attn_mma_kernel<<<dim3(16, 32, 2), 256, A_SMEM>>>(
        (const uint32_t*)qhp, (const uint32_t*)qlp,
        (const uint32_t*)khp, (const uint32_t*)vhp,
        (uint32_t*)ahp, (uint32_t*)alp);

    // 4) output projection
    gemm_out_kernel<<<dim3(16, 32), 256, GB_SMEM>>>(ahp, alp, woh, out);
}